// round 1
// baseline (speedup 1.0000x reference)
#include <cuda_runtime.h>
#include <math.h>
#include <stdint.h>

// ---------------------------------------------------------------------------
// Transformer-XL block, fp32 baseline.
// Shapes (fixed by the problem instance):
//   B=4, T=1024, M=1024, D=1024, H=16, dh=64, L=T+M=2048, Dff=4096
// Outputs: y [B,T,D] followed by new_mem [B,1024,D].
// new_mem == x exactly (concat([mem,x])[:, -1024:] with M==T==1024).
// ---------------------------------------------------------------------------

#define NB   4
#define NT   1024
#define NM   1024
#define ND   1024
#define NH   16
#define NDH  64
#define NL   2048          // T + M
#define NDFF 4096

#define BTD  ((size_t)NB * NT * ND)        // 4194304
#define BLD  ((size_t)NB * NL * ND)        // 8388608
#define SCSZ ((size_t)NB * NH * NT * NL)   // 134217728

// -------------------------- scratch (device globals) -----------------------
__device__ float g_xn [BTD];
__device__ float g_cat[BLD];
__device__ float g_q  [BTD];
__device__ float g_k  [BLD];
__device__ float g_v  [BLD];
__device__ float g_pe [(size_t)NL * ND];
__device__ float g_r  [(size_t)NL * ND];
__device__ float g_scores[SCSZ];           // content -> attn (in place)
__device__ float g_rel   [SCSZ];           // raw rel logits (pre-shift)
__device__ float g_ctx[BTD];
__device__ float g_x2 [BTD];
__device__ float g_xf [BTD];
__device__ float g_ffh[(size_t)NB * NT * NDFF];

// ------------------------------ helpers ------------------------------------
__device__ __forceinline__ float gelu_exact(float v) {
    return 0.5f * v * (1.0f + erff(v * 0.70710678118654752f));
}

// ------------------------------ pos emb ------------------------------------
__global__ void pe_kernel(float* __restrict__ pe) {
    int idx = blockIdx.x * blockDim.x + threadIdx.x;
    if (idx >= NL * ND) return;
    int l = idx / ND, d = idx % ND;
    float pos = (float)(NL - 1 - l);
    int j = (d < ND / 2) ? d : d - ND / 2;
    // inv_freq = 10000 ** (-(2j)/D)
    float invf = powf(10000.0f, -(2.0f * (float)j) / (float)ND);
    float a = pos * invf;
    pe[idx] = (d < ND / 2) ? sinf(a) : cosf(a);
}

// ------------------------------ layer norm ---------------------------------
// one block (256 thr) per row of D=1024
__global__ void ln_kernel(const float* __restrict__ x, const float* __restrict__ g,
                          const float* __restrict__ b, float* __restrict__ out) {
    int row = blockIdx.x;
    const float* xr = x + (size_t)row * ND;
    int tid = threadIdx.x;
    float v[4];
    float s = 0.f;
#pragma unroll
    for (int i = 0; i < 4; i++) { v[i] = xr[tid + i * 256]; s += v[i]; }
    __shared__ float red[256];
    red[tid] = s; __syncthreads();
    for (int o = 128; o > 0; o >>= 1) { if (tid < o) red[tid] += red[tid + o]; __syncthreads(); }
    float mu = red[0] * (1.0f / ND);
    __syncthreads();
    float s2 = 0.f;
#pragma unroll
    for (int i = 0; i < 4; i++) { float t = v[i] - mu; s2 += t * t; }
    red[tid] = s2; __syncthreads();
    for (int o = 128; o > 0; o >>= 1) { if (tid < o) red[tid] += red[tid + o]; __syncthreads(); }
    float rstd = rsqrtf(red[0] * (1.0f / ND) + 1e-5f);
    float* orow = out + (size_t)row * ND;
#pragma unroll
    for (int i = 0; i < 4; i++) {
        int c = tid + i * 256;
        orow[c] = (v[i] - mu) * rstd * g[c] + b[c];
    }
}

// ------------------------- cat = [mem ; xn] --------------------------------
__global__ void cat_kernel(const float* __restrict__ mem, const float* __restrict__ xn,
                           float* __restrict__ cat) {
    size_t idx = (size_t)blockIdx.x * blockDim.x + threadIdx.x;
    if (idx >= BLD) return;
    size_t b = idx / ((size_t)NL * ND);
    size_t rem = idx - b * (size_t)NL * ND;
    int l = (int)(rem / ND);
    int d = (int)(rem % ND);
    float val;
    if (l < NM) val = mem[(b * NM + l) * ND + d];
    else        val = xn [(b * NT + (l - NM)) * ND + d];
    cat[idx] = val;
}

// ------------------------------ generic SGEMM ------------------------------
// C[M,N] = A[M,K] @ W[K,N]  (+ epilogue). All dims multiples of 64/16.
// EPI: 0 none, 1 +bias, 2 +bias then gelu, 3 +res, 4 +bias +res
template <int EPI>
__global__ void sgemm_kernel(const float* __restrict__ A, const float* __restrict__ W,
                             float* __restrict__ C, int M, int N, int K,
                             const float* __restrict__ bias, const float* __restrict__ res) {
    const int BM = 64, BN = 64, BK = 16;
    __shared__ float As[BK][BM + 1];
    __shared__ float Ws[BK][BN + 1];
    int tid = threadIdx.x;
    int tx = tid & 15, ty = tid >> 4;
    int m0 = blockIdx.y * BM, n0 = blockIdx.x * BN;
    float acc[4][4] = {};
    for (int k0 = 0; k0 < K; k0 += BK) {
#pragma unroll
        for (int t = tid; t < BM * BK; t += 256) {
            int m = t >> 4, k = t & 15;
            As[k][m] = A[(size_t)(m0 + m) * K + k0 + k];
        }
#pragma unroll
        for (int t = tid; t < BK * BN; t += 256) {
            int k = t >> 6, n = t & 63;
            Ws[k][n] = W[(size_t)(k0 + k) * N + n0 + n];
        }
        __syncthreads();
#pragma unroll
        for (int k = 0; k < BK; k++) {
            float a[4], bv[4];
#pragma unroll
            for (int i = 0; i < 4; i++) a[i] = As[k][ty * 4 + i];
#pragma unroll
            for (int j = 0; j < 4; j++) bv[j] = Ws[k][tx * 4 + j];
#pragma unroll
            for (int i = 0; i < 4; i++)
#pragma unroll
                for (int j = 0; j < 4; j++) acc[i][j] += a[i] * bv[j];
        }
        __syncthreads();
    }
#pragma unroll
    for (int i = 0; i < 4; i++) {
        int m = m0 + ty * 4 + i;
#pragma unroll
        for (int j = 0; j < 4; j++) {
            int n = n0 + tx * 4 + j;
            float v = acc[i][j];
            if (EPI == 1 || EPI == 2 || EPI == 4) v += bias[n];
            if (EPI == 2) v = gelu_exact(v);
            if (EPI == 3 || EPI == 4) v += res[(size_t)m * N + n];
            C[(size_t)m * N + n] = v;
        }
    }
}

// --------------------- attention logits (content / rel) --------------------
// out[bh, i, j] = sum_d (q[b,i,h,d] + bias[h,d]) * KR[row j][h,d]
// per_batch=1: KR row base = b*L (k matrix);  per_batch=0: KR = r (shared over b)
__global__ void score_kernel(const float* __restrict__ q, const float* __restrict__ kr,
                             const float* __restrict__ bias, float* __restrict__ out,
                             int per_batch) {
    int bh = blockIdx.z;
    int b = bh >> 4, h = bh & 15;
    int i0 = blockIdx.y * 64, j0 = blockIdx.x * 64;
    const float* Abase = q + ((size_t)b * NT) * ND + h * NDH;
    const float* Bbase = kr + (per_batch ? ((size_t)b * NL) * ND : (size_t)0) + h * NDH;
    const float* bia = bias + h * NDH;

    __shared__ float As[16][65];   // [k][i]
    __shared__ float Bs[64][17];   // [j][k]
    int tid = threadIdx.x;
    int tx = tid & 15, ty = tid >> 4;
    float acc[4][4] = {};
#pragma unroll
    for (int kk0 = 0; kk0 < NDH; kk0 += 16) {
#pragma unroll
        for (int t = tid; t < 64 * 16; t += 256) {
            int i = t >> 4, k = t & 15;
            As[k][i] = Abase[(size_t)(i0 + i) * ND + kk0 + k] + bia[kk0 + k];
        }
#pragma unroll
        for (int t = tid; t < 64 * 16; t += 256) {
            int j = t >> 4, k = t & 15;
            Bs[j][k] = Bbase[(size_t)(j0 + j) * ND + kk0 + k];
        }
        __syncthreads();
#pragma unroll
        for (int k = 0; k < 16; k++) {
            float a[4], bv[4];
#pragma unroll
            for (int i = 0; i < 4; i++) a[i] = As[k][ty * 4 + i];
#pragma unroll
            for (int j = 0; j < 4; j++) bv[j] = Bs[tx * 4 + j][k];
#pragma unroll
            for (int i = 0; i < 4; i++)
#pragma unroll
                for (int j = 0; j < 4; j++) acc[i][j] += a[i] * bv[j];
        }
        __syncthreads();
    }
#pragma unroll
    for (int i = 0; i < 4; i++)
#pragma unroll
        for (int j = 0; j < 4; j++)
            out[((size_t)bh * NT + i0 + ty * 4 + i) * NL + j0 + tx * 4 + j] = acc[i][j];
}

// ------------------- softmax((content + shift(rel)) * scale) ---------------
// one block (256 thr) per (b,h,i) row of length L=2048
__global__ void softmax_kernel(float* __restrict__ scores, const float* __restrict__ rel) {
    int row = blockIdx.x;                  // (b*H+h)*T + i
    int i = row & (NT - 1);
    int bh = row >> 10;                    // NT = 1024
    float* srow = scores + (size_t)row * NL;
    const float* relbase = rel + (size_t)bh * NT * NL;
    int tid = threadIdx.x;

    float vals[8];
    float mx = -1e30f;
#pragma unroll
    for (int t = 0; t < 8; t++) {
        int j = tid + t * 256;
        long flat = (long)NT + (long)i * NL + j;
        int p = (int)(flat / (NL + 1));
        int qq = (int)(flat % (NL + 1));
        float rl = (qq == 0) ? 0.f : relbase[(size_t)p * NL + (qq - 1)];
        float v = (srow[j] + rl) * 0.125f;          // scale = 1/sqrt(64)
        vals[t] = v;
        mx = fmaxf(mx, v);
    }
    __shared__ float red[256];
    red[tid] = mx; __syncthreads();
    for (int o = 128; o > 0; o >>= 1) { if (tid < o) red[tid] = fmaxf(red[tid], red[tid + o]); __syncthreads(); }
    mx = red[0]; __syncthreads();
    float sum = 0.f;
#pragma unroll
    for (int t = 0; t < 8; t++) { vals[t] = expf(vals[t] - mx); sum += vals[t]; }
    red[tid] = sum; __syncthreads();
    for (int o = 128; o > 0; o >>= 1) { if (tid < o) red[tid] += red[tid + o]; __syncthreads(); }
    float inv = 1.0f / red[0];
#pragma unroll
    for (int t = 0; t < 8; t++) srow[tid + t * 256] = vals[t] * inv;
}

// ------------------------------ attn @ v -----------------------------------
// ctx[b, i, h, d] = sum_j attn[bh, i, j] * v[b, j, h, d]
__global__ void attnv_kernel(const float* __restrict__ attn, const float* __restrict__ v,
                             float* __restrict__ ctx) {
    int bh = blockIdx.y;
    int b = bh >> 4, h = bh & 15;
    int i0 = blockIdx.x * 64;
    __shared__ float As[64][17];   // [i][k]
    __shared__ float Vs[16][65];   // [k][d]
    int tid = threadIdx.x;
    int tx = tid & 15, ty = tid >> 4;
    float acc[4][4] = {};
    const float* arow = attn + ((size_t)bh * NT + i0) * NL;
    const float* vbase = v + ((size_t)b * NL) * ND + h * NDH;
    for (int j0 = 0; j0 < NL; j0 += 16) {
#pragma unroll
        for (int t = tid; t < 64 * 16; t += 256) {
            int i = t >> 4, k = t & 15;
            As[i][k] = arow[(size_t)i * NL + j0 + k];
        }
#pragma unroll
        for (int t = tid; t < 16 * 64; t += 256) {
            int k = t >> 6, d = t & 63;
            Vs[k][d] = vbase[(size_t)(j0 + k) * ND + d];
        }
        __syncthreads();
#pragma unroll
        for (int k = 0; k < 16; k++) {
            float a[4], bv[4];
#pragma unroll
            for (int i = 0; i < 4; i++) a[i] = As[ty * 4 + i][k];
#pragma unroll
            for (int j = 0; j < 4; j++) bv[j] = Vs[k][tx * 4 + j];
#pragma unroll
            for (int i = 0; i < 4; i++)
#pragma unroll
                for (int j = 0; j < 4; j++) acc[i][j] += a[i] * bv[j];
        }
        __syncthreads();
    }
#pragma unroll
    for (int i = 0; i < 4; i++)
#pragma unroll
        for (int j = 0; j < 4; j++)
            ctx[((size_t)b * NT + i0 + ty * 4 + i) * ND + h * NDH + tx * 4 + j] = acc[i][j];
}

// ------------------------------ launch -------------------------------------
extern "C" void kernel_launch(void* const* d_in, const int* in_sizes, int n_in,
                              void* d_out, int out_size) {
    const float* x      = (const float*)d_in[0];
    const float* mem    = (const float*)d_in[1];
    const float* Wq     = (const float*)d_in[2];
    const float* Wk     = (const float*)d_in[3];
    const float* Wv     = (const float*)d_in[4];
    const float* Wr     = (const float*)d_in[5];
    const float* Wo     = (const float*)d_in[6];
    const float* bias_u = (const float*)d_in[7];
    const float* bias_v = (const float*)d_in[8];
    const float* ln1_g  = (const float*)d_in[9];
    const float* ln1_b  = (const float*)d_in[10];
    const float* ln2_g  = (const float*)d_in[11];
    const float* ln2_b  = (const float*)d_in[12];
    const float* W1     = (const float*)d_in[13];
    const float* b1     = (const float*)d_in[14];
    const float* W2     = (const float*)d_in[15];
    const float* b2     = (const float*)d_in[16];
    float* out = (float*)d_out;

    float *xn, *cat, *q, *k, *v, *pe, *r, *scores, *rel, *ctx, *x2, *xf, *ffh;
    cudaGetSymbolAddress((void**)&xn,     g_xn);
    cudaGetSymbolAddress((void**)&cat,    g_cat);
    cudaGetSymbolAddress((void**)&q,      g_q);
    cudaGetSymbolAddress((void**)&k,      g_k);
    cudaGetSymbolAddress((void**)&v,      g_v);
    cudaGetSymbolAddress((void**)&pe,     g_pe);
    cudaGetSymbolAddress((void**)&r,      g_r);
    cudaGetSymbolAddress((void**)&scores, g_scores);
    cudaGetSymbolAddress((void**)&rel,    g_rel);
    cudaGetSymbolAddress((void**)&ctx,    g_ctx);
    cudaGetSymbolAddress((void**)&x2,     g_x2);
    cudaGetSymbolAddress((void**)&xf,     g_xf);
    cudaGetSymbolAddress((void**)&ffh,    g_ffh);

    // 1. positional embedding pe[L,D]
    pe_kernel<<<(NL * ND + 255) / 256, 256>>>(pe);
    // 2. xn = LN1(x)
    ln_kernel<<<NB * NT, 256>>>(x, ln1_g, ln1_b, xn);
    // 3. cat = [mem ; xn]
    cat_kernel<<<(unsigned)((BLD + 255) / 256), 256>>>(mem, xn, cat);
    // 4. projections
    sgemm_kernel<0><<<dim3(ND / 64, (NB * NT) / 64), 256>>>(xn,  Wq, q, NB * NT, ND, ND, nullptr, nullptr);
    sgemm_kernel<0><<<dim3(ND / 64, (NB * NL) / 64), 256>>>(cat, Wk, k, NB * NL, ND, ND, nullptr, nullptr);
    sgemm_kernel<0><<<dim3(ND / 64, (NB * NL) / 64), 256>>>(cat, Wv, v, NB * NL, ND, ND, nullptr, nullptr);
    sgemm_kernel<0><<<dim3(ND / 64, NL / 64), 256>>>(pe, Wr, r, NL, ND, ND, nullptr, nullptr);
    // 5. attention logits
    score_kernel<<<dim3(NL / 64, NT / 64, NB * NH), 256>>>(q, k, bias_u, scores, 1);
    score_kernel<<<dim3(NL / 64, NT / 64, NB * NH), 256>>>(q, r, bias_v, rel, 0);
    // 6. softmax with rel-shift fused
    softmax_kernel<<<NB * NH * NT, 256>>>(scores, rel);
    // 7. context
    attnv_kernel<<<dim3(NT / 64, NB * NH), 256>>>(scores, v, ctx);
    // 8. output proj + residual -> x2
    sgemm_kernel<3><<<dim3(ND / 64, (NB * NT) / 64), 256>>>(ctx, Wo, x2, NB * NT, ND, ND, nullptr, x);
    // 9. LN2
    ln_kernel<<<NB * NT, 256>>>(x2, ln2_g, ln2_b, xf);
    // 10. FFN
    sgemm_kernel<2><<<dim3(NDFF / 64, (NB * NT) / 64), 256>>>(xf,  W1, ffh, NB * NT, NDFF, ND,  b1, nullptr);
    sgemm_kernel<4><<<dim3(ND / 64, (NB * NT) / 64), 256>>>(ffh, W2, out, NB * NT, ND, NDFF, b2, x2);
    // 11. new_mem = x  (concat([mem,x])[:, -1024:] with M == T == MEM_LEN)
    if ((size_t)out_size >= 2 * BTD) {
        cudaMemcpyAsync(out + BTD, x, BTD * sizeof(float), cudaMemcpyDeviceToDevice);
    }
}

// round 3
// speedup vs baseline: 1.4008x; 1.4008x over previous
#include <cuda_runtime.h>
#include <math.h>
#include <stdint.h>

// ---------------------------------------------------------------------------
// Transformer-XL block. 3xTF32 tensor-core GEMMs (mma.sync.m16n8k8.tf32),
// fp32 everything else.
//   B=4, T=1024, M=1024, D=1024, H=16, dh=64, L=2048, Dff=4096
// Outputs: y [B,T,D] then new_mem [B,1024,D] == x.
// ---------------------------------------------------------------------------

#define NB   4
#define NT   1024
#define NM   1024
#define ND   1024
#define NH   16
#define NDH  64
#define NL   2048
#define NDFF 4096

#define BTD  ((size_t)NB * NT * ND)
#define BLD  ((size_t)NB * NL * ND)
#define SCSZ ((size_t)NB * NH * NT * NL)

// -------------------------- scratch (device globals) -----------------------
__device__ float g_xn [BTD];
__device__ float g_cat[BLD];
__device__ float g_q  [BTD];
__device__ float g_k  [BLD];
__device__ float g_v  [BLD];
__device__ float g_pe [(size_t)NL * ND];
__device__ float g_r  [(size_t)NL * ND];
__device__ float g_scores[SCSZ];
__device__ float g_rel   [SCSZ];
__device__ float g_ctx[BTD];
__device__ float g_x2 [BTD];
__device__ float g_xf [BTD];
__device__ float g_ffh[(size_t)NB * NT * NDFF];

// ------------------------------ helpers ------------------------------------
__device__ __forceinline__ float gelu_exact(float v) {
    return 0.5f * v * (1.0f + erff(v * 0.70710678118654752f));
}

__device__ __forceinline__ uint32_t f2tf(float f) {
    uint32_t r; asm("cvt.rna.tf32.f32 %0, %1;" : "=r"(r) : "f"(f)); return r;
}

__device__ __forceinline__ void split_tf32(float v, uint32_t& hi, uint32_t& lo) {
    uint32_t h = f2tf(v);
    hi = h;
    lo = f2tf(v - __uint_as_float(h));
}

__device__ __forceinline__ void mma8(float* c, const uint32_t* a, const uint32_t* b) {
    asm volatile("mma.sync.aligned.m16n8k8.row.col.f32.tf32.tf32.f32 "
        "{%0,%1,%2,%3}, {%4,%5,%6,%7}, {%8,%9}, {%0,%1,%2,%3};\n"
        : "+f"(c[0]), "+f"(c[1]), "+f"(c[2]), "+f"(c[3])
        : "r"(a[0]), "r"(a[1]), "r"(a[2]), "r"(a[3]), "r"(b[0]), "r"(b[1]));
}

// ------------------------------ pos emb ------------------------------------
__global__ void pe_kernel(float* __restrict__ pe) {
    int idx = blockIdx.x * blockDim.x + threadIdx.x;
    if (idx >= NL * ND) return;
    int l = idx / ND, d = idx % ND;
    float pos = (float)(NL - 1 - l);
    int j = (d < ND / 2) ? d : d - ND / 2;
    float invf = powf(10000.0f, -(2.0f * (float)j) / (float)ND);
    float a = pos * invf;
    pe[idx] = (d < ND / 2) ? sinf(a) : cosf(a);
}

// ------------------------------ layer norm ---------------------------------
__global__ void ln_kernel(const float* __restrict__ x, const float* __restrict__ g,
                          const float* __restrict__ b, float* __restrict__ out) {
    int row = blockIdx.x;
    const float* xr = x + (size_t)row * ND;
    int tid = threadIdx.x;
    float v[4];
    float s = 0.f;
#pragma unroll
    for (int i = 0; i < 4; i++) { v[i] = xr[tid + i * 256]; s += v[i]; }
    __shared__ float red[256];
    red[tid] = s; __syncthreads();
    for (int o = 128; o > 0; o >>= 1) { if (tid < o) red[tid] += red[tid + o]; __syncthreads(); }
    float mu = red[0] * (1.0f / ND);
    __syncthreads();
    float s2 = 0.f;
#pragma unroll
    for (int i = 0; i < 4; i++) { float t = v[i] - mu; s2 += t * t; }
    red[tid] = s2; __syncthreads();
    for (int o = 128; o > 0; o >>= 1) { if (tid < o) red[tid] += red[tid + o]; __syncthreads(); }
    float rstd = rsqrtf(red[0] * (1.0f / ND) + 1e-5f);
    float* orow = out + (size_t)row * ND;
#pragma unroll
    for (int i = 0; i < 4; i++) {
        int c = tid + i * 256;
        orow[c] = (v[i] - mu) * rstd * g[c] + b[c];
    }
}

// ------------------------- cat = [mem ; xn] --------------------------------
__global__ void cat_kernel(const float* __restrict__ mem, const float* __restrict__ xn,
                           float* __restrict__ cat) {
    size_t idx = (size_t)blockIdx.x * blockDim.x + threadIdx.x;
    if (idx >= BLD) return;
    size_t b = idx / ((size_t)NL * ND);
    size_t rem = idx - b * (size_t)NL * ND;
    int l = (int)(rem / ND);
    int d = (int)(rem % ND);
    float val;
    if (l < NM) val = mem[(b * NM + l) * ND + d];
    else        val = xn [(b * NT + (l - NM)) * ND + d];
    cat[idx] = val;
}

// ------------------------- 3xTF32 mma GEMM core ----------------------------
// C[.., N] = A[M,K] @ B  (+ epilogue). BM=128, BK=16.
// TRANSB=0: B global [K,N] row-major.  TRANSB=1: B global [N,K] row-major.
// EPI: 0 store, 1 +res, 2 +bias->gelu, 3 +bias +res
// BIASA: add biasA[k] to A elements before use (q + bias_u/v fusion).
template<int BN, int MF, int NF, int TRANSB, int EPI, bool BIASA>
__device__ __forceinline__ void mm_core(
    const float* __restrict__ A, const float* __restrict__ B, float* __restrict__ C,
    int K, int lda, int ldb, int ldc,
    const float* __restrict__ biasA, const float* __restrict__ biasC,
    const float* __restrict__ resC)
{
    constexpr int BM = 128, BK = 16;
    __shared__ uint32_t Ah[BK * BM];
    __shared__ uint32_t Al[BK * BM];
    __shared__ uint32_t Bh[BK * BN];
    __shared__ uint32_t Bl[BK * BN];

    const int tid  = threadIdx.x;
    const int lane = tid & 31;
    const int w    = tid >> 5;
    constexpr int WARPS_M = BM / (MF * 16);
    const int wm = w % WARPS_M;
    const int wn = w / WARPS_M;
    const int mBase = wm * MF * 16;
    const int nBase = wn * NF * 8;
    const int m0 = blockIdx.y * BM;
    const int n0 = blockIdx.x * BN;
    const int tig = lane & 3;
    const int gid = lane >> 2;

    float acc[MF][NF][4];
#pragma unroll
    for (int i = 0; i < MF; i++)
#pragma unroll
        for (int j = 0; j < NF; j++)
#pragma unroll
            for (int r = 0; r < 4; r++) acc[i][j][r] = 0.f;

    for (int k0 = 0; k0 < K; k0 += BK) {
        // ---- A tile: BM x BK, float4 along K ----
#pragma unroll
        for (int i = 0; i < (BM * BK / 4) / 256; i++) {
            int idx = tid + i * 256;
            int row = idx >> 2;
            int c4  = idx & 3;
            float4 vv = *reinterpret_cast<const float4*>(
                A + (size_t)(m0 + row) * lda + k0 + c4 * 4);
            if (BIASA) {
                int kk = k0 + c4 * 4;
                vv.x += biasA[kk]; vv.y += biasA[kk + 1];
                vv.z += biasA[kk + 2]; vv.w += biasA[kk + 3];
            }
            int kb = c4 * 4;
#pragma unroll
            for (int j = 0; j < 4; j++) {
                int k = kb + j;
                int msk = ((k & 3) << 3) ^ ((k >> 2) & 7);
                float fv = (j == 0) ? vv.x : (j == 1) ? vv.y : (j == 2) ? vv.z : vv.w;
                uint32_t hi, lo; split_tf32(fv, hi, lo);
                Ah[k * BM + (row ^ msk)] = hi;
                Al[k * BM + (row ^ msk)] = lo;
            }
        }
        // ---- B tile ----
        if (TRANSB == 0) {
#pragma unroll
            for (int i = 0; i < (BN * BK / 4) / 256; i++) {
                int idx = tid + i * 256;
                int k  = idx / (BN / 4);
                int c4 = idx % (BN / 4);
                float4 vv = *reinterpret_cast<const float4*>(
                    B + (size_t)(k0 + k) * ldb + n0 + c4 * 4);
                uint4 oh, ol;
                split_tf32(vv.x, oh.x, ol.x);
                split_tf32(vv.y, oh.y, ol.y);
                split_tf32(vv.z, oh.z, ol.z);
                split_tf32(vv.w, oh.w, ol.w);
                int base = k * BN + ((c4 * 4) ^ ((k & 3) << 3));
                *reinterpret_cast<uint4*>(&Bh[base]) = oh;
                *reinterpret_cast<uint4*>(&Bl[base]) = ol;
            }
        } else {
#pragma unroll
            for (int i = 0; i < (BN * BK / 4) / 256; i++) {
                int idx = tid + i * 256;
                int n  = idx >> 2;
                int c4 = idx & 3;
                float4 vv = *reinterpret_cast<const float4*>(
                    B + (size_t)(n0 + n) * ldb + k0 + c4 * 4);
#pragma unroll
                for (int j = 0; j < 4; j++) {
                    int k = c4 * 4 + j;
                    int msk = ((k & 3) << 3) ^ ((k >> 2) & 7);
                    float fv = (j == 0) ? vv.x : (j == 1) ? vv.y : (j == 2) ? vv.z : vv.w;
                    uint32_t hi, lo; split_tf32(fv, hi, lo);
                    Bh[k * BN + (n ^ msk)] = hi;
                    Bl[k * BN + (n ^ msk)] = lo;
                }
            }
        }
        __syncthreads();

#pragma unroll
        for (int ks = 0; ks < BK / 8; ks++) {
            int kA  = ks * 8 + tig;
            int kA2 = kA + 4;
            int mskA1 = ((kA  & 3) << 3) ^ ((kA  >> 2) & 7);
            int mskA2 = ((kA2 & 3) << 3) ^ ((kA2 >> 2) & 7);
            int mskB1 = (TRANSB == 0) ? ((kA  & 3) << 3) : mskA1;
            int mskB2 = (TRANSB == 0) ? ((kA2 & 3) << 3) : mskA2;

            uint32_t ah[MF][4], al[MF][4], bh[NF][2], bl[NF][2];
#pragma unroll
            for (int mf = 0; mf < MF; mf++) {
                int m = mBase + mf * 16 + gid;
                ah[mf][0] = Ah[kA  * BM + ( m      ^ mskA1)];
                ah[mf][1] = Ah[kA  * BM + ((m + 8) ^ mskA1)];
                ah[mf][2] = Ah[kA2 * BM + ( m      ^ mskA2)];
                ah[mf][3] = Ah[kA2 * BM + ((m + 8) ^ mskA2)];
                al[mf][0] = Al[kA  * BM + ( m      ^ mskA1)];
                al[mf][1] = Al[kA  * BM + ((m + 8) ^ mskA1)];
                al[mf][2] = Al[kA2 * BM + ( m      ^ mskA2)];
                al[mf][3] = Al[kA2 * BM + ((m + 8) ^ mskA2)];
            }
#pragma unroll
            for (int nf = 0; nf < NF; nf++) {
                int n = nBase + nf * 8 + gid;
                bh[nf][0] = Bh[kA  * BN + (n ^ mskB1)];
                bh[nf][1] = Bh[kA2 * BN + (n ^ mskB2)];
                bl[nf][0] = Bl[kA  * BN + (n ^ mskB1)];
                bl[nf][1] = Bl[kA2 * BN + (n ^ mskB2)];
            }
#pragma unroll
            for (int mf = 0; mf < MF; mf++)
#pragma unroll
                for (int nf = 0; nf < NF; nf++) {
                    mma8(acc[mf][nf], ah[mf], bh[nf]);
                    mma8(acc[mf][nf], al[mf], bh[nf]);
                    mma8(acc[mf][nf], ah[mf], bl[nf]);
                }
        }
        __syncthreads();
    }

    // ---- epilogue ----
#pragma unroll
    for (int mf = 0; mf < MF; mf++) {
#pragma unroll
        for (int nf = 0; nf < NF; nf++) {
#pragma unroll
            for (int r = 0; r < 4; r++) {
                int m = m0 + mBase + mf * 16 + gid + ((r & 2) ? 8 : 0);
                int n = n0 + nBase + nf * 8 + tig * 2 + (r & 1);
                float v = acc[mf][nf][r];
                if (EPI == 2 || EPI == 3) v += biasC[n];
                if (EPI == 2) v = gelu_exact(v);
                if (EPI == 1 || EPI == 3) v += resC[(size_t)m * ldc + n];
                C[(size_t)m * ldc + n] = v;
            }
        }
    }
}

// ------------------------------ wrappers -----------------------------------
template<int EPI>
__global__ __launch_bounds__(256) void gemm_plain(
    const float* __restrict__ A, const float* __restrict__ B, float* __restrict__ C,
    int K, int lda, int ldb, int ldc,
    const float* __restrict__ biasC, const float* __restrict__ resC)
{
    mm_core<128, 4, 4, 0, EPI, false>(A, B, C, K, lda, ldb, ldc, nullptr, biasC, resC);
}

template<int PER_BATCH>
__global__ __launch_bounds__(256) void score_mma(
    const float* __restrict__ q, const float* __restrict__ kr,
    const float* __restrict__ bias, float* __restrict__ out)
{
    int bh = blockIdx.z, b = bh >> 4, h = bh & 15;
    const float* Ab = q + ((size_t)b * NT) * ND + h * NDH;
    const float* Bb = kr + (PER_BATCH ? ((size_t)b * NL) * ND : (size_t)0) + h * NDH;
    float* Cb = out + (size_t)bh * NT * NL;
    mm_core<128, 4, 4, 1, 0, true>(Ab, Bb, Cb, NDH, ND, ND, NL,
                                   bias + h * NDH, nullptr, nullptr);
}

__global__ __launch_bounds__(256) void attnv_mma(
    const float* __restrict__ attn, const float* __restrict__ v, float* __restrict__ ctx)
{
    int bh = blockIdx.z, b = bh >> 4, h = bh & 15;
    const float* Ab = attn + (size_t)bh * NT * NL;
    const float* Bb = v + ((size_t)b * NL) * ND + h * NDH;
    float* Cb = ctx + ((size_t)b * NT) * ND + h * NDH;
    mm_core<64, 2, 4, 0, 0, false>(Ab, Bb, Cb, NL, NL, ND, ND,
                                   nullptr, nullptr, nullptr);
}

// ------------------- softmax((content + shift(rel)) * scale) ---------------
__global__ void softmax_kernel(float* __restrict__ scores, const float* __restrict__ rel) {
    int row = blockIdx.x;                  // (b*H+h)*T + i
    int i = row & (NT - 1);
    int bh = row >> 10;
    float* srow = scores + (size_t)row * NL;
    const float* relbase = rel + (size_t)bh * NT * NL;
    int tid = threadIdx.x;

    float vals[8];
    float mx = -1e30f;
#pragma unroll
    for (int t = 0; t < 8; t++) {
        int j = tid + t * 256;
        long flat = (long)NT + (long)i * NL + j;
        int p  = (int)(flat / (NL + 1));
        int qq = (int)(flat % (NL + 1));
        float rl = (qq == 0) ? 0.f : relbase[(size_t)p * NL + (qq - 1)];
        float v = (srow[j] + rl) * 0.125f;
        vals[t] = v;
        mx = fmaxf(mx, v);
    }
    __shared__ float red[256];
    red[tid] = mx; __syncthreads();
    for (int o = 128; o > 0; o >>= 1) { if (tid < o) red[tid] = fmaxf(red[tid], red[tid + o]); __syncthreads(); }
    mx = red[0]; __syncthreads();
    float sum = 0.f;
#pragma unroll
    for (int t = 0; t < 8; t++) { vals[t] = expf(vals[t] - mx); sum += vals[t]; }
    red[tid] = sum; __syncthreads();
    for (int o = 128; o > 0; o >>= 1) { if (tid < o) red[tid] += red[tid + o]; __syncthreads(); }
    float inv = 1.0f / red[0];
#pragma unroll
    for (int t = 0; t < 8; t++) srow[tid + t * 256] = vals[t] * inv;
}

// ------------------------------ launch -------------------------------------
extern "C" void kernel_launch(void* const* d_in, const int* in_sizes, int n_in,
                              void* d_out, int out_size) {
    const float* x      = (const float*)d_in[0];
    const float* mem    = (const float*)d_in[1];
    const float* Wq     = (const float*)d_in[2];
    const float* Wk     = (const float*)d_in[3];
    const float* Wv     = (const float*)d_in[4];
    const float* Wr     = (const float*)d_in[5];
    const float* Wo     = (const float*)d_in[6];
    const float* bias_u = (const float*)d_in[7];
    const float* bias_v = (const float*)d_in[8];
    const float* ln1_g  = (const float*)d_in[9];
    const float* ln1_b  = (const float*)d_in[10];
    const float* ln2_g  = (const float*)d_in[11];
    const float* ln2_b  = (const float*)d_in[12];
    const float* W1     = (const float*)d_in[13];
    const float* b1     = (const float*)d_in[14];
    const float* W2     = (const float*)d_in[15];
    const float* b2     = (const float*)d_in[16];
    float* out = (float*)d_out;

    float *xn, *cat, *q, *k, *v, *pe, *r, *scores, *rel, *ctx, *x2, *xf, *ffh;
    cudaGetSymbolAddress((void**)&xn,     g_xn);
    cudaGetSymbolAddress((void**)&cat,    g_cat);
    cudaGetSymbolAddress((void**)&q,      g_q);
    cudaGetSymbolAddress((void**)&k,      g_k);
    cudaGetSymbolAddress((void**)&v,      g_v);
    cudaGetSymbolAddress((void**)&pe,     g_pe);
    cudaGetSymbolAddress((void**)&r,      g_r);
    cudaGetSymbolAddress((void**)&scores, g_scores);
    cudaGetSymbolAddress((void**)&rel,    g_rel);
    cudaGetSymbolAddress((void**)&ctx,    g_ctx);
    cudaGetSymbolAddress((void**)&x2,     g_x2);
    cudaGetSymbolAddress((void**)&xf,     g_xf);
    cudaGetSymbolAddress((void**)&ffh,    g_ffh);

    pe_kernel<<<(NL * ND + 255) / 256, 256>>>(pe);
    ln_kernel<<<NB * NT, 256>>>(x, ln1_g, ln1_b, xn);
    cat_kernel<<<(unsigned)((BLD + 255) / 256), 256>>>(mem, xn, cat);

    // projections (3xTF32 mma)
    gemm_plain<0><<<dim3(ND / 128,   (NB * NT) / 128), 256>>>(xn,  Wq, q, ND, ND, ND, ND, nullptr, nullptr);
    gemm_plain<0><<<dim3(ND / 128,   (NB * NL) / 128), 256>>>(cat, Wk, k, ND, ND, ND, ND, nullptr, nullptr);
    gemm_plain<0><<<dim3(ND / 128,   (NB * NL) / 128), 256>>>(cat, Wv, v, ND, ND, ND, ND, nullptr, nullptr);
    gemm_plain<0><<<dim3(ND / 128,   NL / 128),        256>>>(pe,  Wr, r, ND, ND, ND, ND, nullptr, nullptr);

    // attention logits
    score_mma<1><<<dim3(NL / 128, NT / 128, NB * NH), 256>>>(q, k, bias_u, scores);
    score_mma<0><<<dim3(NL / 128, NT / 128, NB * NH), 256>>>(q, r, bias_v, rel);

    // softmax with fused rel-shift
    softmax_kernel<<<NB * NH * NT, 256>>>(scores, rel);

    // context
    attnv_mma<<<dim3(1, NT / 128, NB * NH), 256>>>(scores, v, ctx);

    // output proj + residual
    gemm_plain<1><<<dim3(ND / 128, (NB * NT) / 128), 256>>>(ctx, Wo, x2, ND, ND, ND, ND, nullptr, x);

    ln_kernel<<<NB * NT, 256>>>(x2, ln2_g, ln2_b, xf);

    // FFN
    gemm_plain<2><<<dim3(NDFF / 128, (NB * NT) / 128), 256>>>(xf,  W1, ffh, ND,   ND,   NDFF, NDFF, b1, nullptr);
    gemm_plain<3><<<dim3(ND / 128,   (NB * NT) / 128), 256>>>(ffh, W2, out, NDFF, NDFF, ND,   ND,   b2, x2);

    // new_mem = x
    if ((size_t)out_size >= 2 * BTD) {
        cudaMemcpyAsync(out + BTD, x, BTD * sizeof(float), cudaMemcpyDeviceToDevice);
    }
}

// round 5
// speedup vs baseline: 2.7836x; 1.9872x over previous
#include <cuda_runtime.h>
#include <cuda_bf16.h>
#include <math.h>
#include <stdint.h>

// ---------------------------------------------------------------------------
// Transformer-XL block. Split-bf16 tensor-core GEMMs:
//   fp32 value = hi(bf16) + lo(bf16);  A*B ~= Ah*Bh + Ah*Bl + Al*Bh
// via mma.sync.m16n8k16.bf16, double-buffered smem, pipelined LDG.
//   B=4, T=1024, M=1024, D=1024, H=16, dh=64, L=2048, Dff=4096
// Outputs: y [B,T,D] then new_mem [B,1024,D] == x.
// ---------------------------------------------------------------------------

#define NB   4
#define NT   1024
#define NM   1024
#define ND   1024
#define NH   16
#define NDH  64
#define NL   2048
#define NDFF 4096

#define BTD  ((size_t)NB * NT * ND)
#define BLD  ((size_t)NB * NL * ND)
#define SCSZ ((size_t)NB * NH * NT * NL)

// -------------------------- scratch (device globals) -----------------------
__device__ float g_xn [BTD];
__device__ float g_cat[BLD];
__device__ float g_q  [BTD];
__device__ float g_k  [BLD];
__device__ float g_v  [BLD];
__device__ float g_pe [(size_t)NL * ND];
__device__ float g_r  [(size_t)NL * ND];
__device__ float g_scores[SCSZ];
__device__ float g_rel   [SCSZ];
__device__ float g_ctx[BTD];
__device__ float g_x2 [BTD];
__device__ float g_xf [BTD];
__device__ float g_ffh[(size_t)NB * NT * NDFF];

// ------------------------------ helpers ------------------------------------
__device__ __forceinline__ float gelu_exact(float v) {
    return 0.5f * v * (1.0f + erff(v * 0.70710678118654752f));
}

// Pack (x -> low16, y -> high16) as bf16x2 hi, and the bf16x2 of residuals.
__device__ __forceinline__ void splitpack(float x, float y, uint32_t& hi, uint32_t& lo) {
    uint32_t h;
    asm("cvt.rn.bf16x2.f32 %0, %1, %2;" : "=r"(h) : "f"(y), "f"(x));
    float hx = __uint_as_float(h << 16);
    float hy = __uint_as_float(h & 0xFFFF0000u);
    uint32_t l;
    asm("cvt.rn.bf16x2.f32 %0, %1, %2;" : "=r"(l) : "f"(y - hy), "f"(x - hx));
    hi = h; lo = l;
}

__device__ __forceinline__ void mma16(float* c, const uint32_t* a, const uint32_t* b) {
    asm volatile("mma.sync.aligned.m16n8k16.row.col.f32.bf16.bf16.f32 "
        "{%0,%1,%2,%3}, {%4,%5,%6,%7}, {%8,%9}, {%0,%1,%2,%3};\n"
        : "+f"(c[0]), "+f"(c[1]), "+f"(c[2]), "+f"(c[3])
        : "r"(a[0]), "r"(a[1]), "r"(a[2]), "r"(a[3]), "r"(b[0]), "r"(b[1]));
}

__device__ __forceinline__ int mskA(int k2) { return ((k2 & 3) << 3) ^ (k2 >> 2); }
__device__ __forceinline__ int mskB(int k2) { return (k2 & 3) << 3; }

// ------------------------------ pos emb ------------------------------------
__global__ void pe_kernel(float* __restrict__ pe) {
    int idx = blockIdx.x * blockDim.x + threadIdx.x;
    if (idx >= NL * ND) return;
    int l = idx / ND, d = idx % ND;
    float pos = (float)(NL - 1 - l);
    int j = (d < ND / 2) ? d : d - ND / 2;
    float invf = powf(10000.0f, -(2.0f * (float)j) / (float)ND);
    float a = pos * invf;
    pe[idx] = (d < ND / 2) ? sinf(a) : cosf(a);
}

// ------------------------------ layer norm ---------------------------------
__global__ void ln_kernel(const float* __restrict__ x, const float* __restrict__ g,
                          const float* __restrict__ b, float* __restrict__ out) {
    int row = blockIdx.x;
    const float* xr = x + (size_t)row * ND;
    int tid = threadIdx.x;
    float v[4];
    float s = 0.f;
#pragma unroll
    for (int i = 0; i < 4; i++) { v[i] = xr[tid + i * 256]; s += v[i]; }
    __shared__ float red[256];
    red[tid] = s; __syncthreads();
    for (int o = 128; o > 0; o >>= 1) { if (tid < o) red[tid] += red[tid + o]; __syncthreads(); }
    float mu = red[0] * (1.0f / ND);
    __syncthreads();
    float s2 = 0.f;
#pragma unroll
    for (int i = 0; i < 4; i++) { float t = v[i] - mu; s2 += t * t; }
    red[tid] = s2; __syncthreads();
    for (int o = 128; o > 0; o >>= 1) { if (tid < o) red[tid] += red[tid + o]; __syncthreads(); }
    float rstd = rsqrtf(red[0] * (1.0f / ND) + 1e-5f);
    float* orow = out + (size_t)row * ND;
#pragma unroll
    for (int i = 0; i < 4; i++) {
        int c = tid + i * 256;
        orow[c] = (v[i] - mu) * rstd * g[c] + b[c];
    }
}

// ------------------------- cat = [mem ; xn] --------------------------------
__global__ void cat_kernel(const float* __restrict__ mem, const float* __restrict__ xn,
                           float* __restrict__ cat) {
    size_t idx = (size_t)blockIdx.x * blockDim.x + threadIdx.x;
    if (idx >= BLD) return;
    size_t b = idx / ((size_t)NL * ND);
    size_t rem = idx - b * (size_t)NL * ND;
    int l = (int)(rem / ND);
    int d = (int)(rem % ND);
    float val;
    if (l < NM) val = mem[(b * NM + l) * ND + d];
    else        val = xn [(b * NT + (l - NM)) * ND + d];
    cat[idx] = val;
}

// ------------------- split-bf16 mma GEMM core (pipelined) ------------------
// C = A[M,K] @ B (+ epilogue). BM=128, BK=16 (8 packed k2 slices).
// TRANSB=0: B global [K,N] row-major.  TRANSB=1: B global [N,K] row-major.
// EPI: 0 store, 1 +res, 2 +bias->gelu, 3 +bias +res
// BIASA: add biasA[k] to A elements before split (q + bias_u/v fusion).
template<int BN, int MF, int NF, int TRANSB, int EPI, bool BIASA>
__device__ __forceinline__ void mm_core(
    const float* __restrict__ A, const float* __restrict__ B, float* __restrict__ C,
    int K, int lda, int ldb, int ldc,
    const float* __restrict__ biasA, const float* __restrict__ biasC,
    const float* __restrict__ resC)
{
    constexpr int BM = 128, BK = 16, BK2 = 8;
    __shared__ __align__(16) uint32_t Ah[2][BK2 * BM];
    __shared__ __align__(16) uint32_t Al[2][BK2 * BM];
    __shared__ __align__(16) uint32_t Bh[2][BK2 * BN];
    __shared__ __align__(16) uint32_t Bl[2][BK2 * BN];

    const int tid  = threadIdx.x;
    const int lane = tid & 31;
    const int w    = tid >> 5;
    constexpr int WARPS_M = BM / (MF * 16);
    const int wm = w % WARPS_M;
    const int wn = w / WARPS_M;
    const int mBase = wm * MF * 16;
    const int nBase = wn * NF * 8;
    const int m0 = blockIdx.y * BM;
    const int n0 = blockIdx.x * BN;
    const int tig = lane & 3;
    const int gid = lane >> 2;

    float acc[MF][NF][4];
#pragma unroll
    for (int i = 0; i < MF; i++)
#pragma unroll
        for (int j = 0; j < NF; j++)
#pragma unroll
            for (int r = 0; r < 4; r++) acc[i][j][r] = 0.f;

    float4 aReg[2];
    float4 bReg[2];
    constexpr int NPAIRS = 2 * BN;          // k2 x n4 pairs in B tile

    // ------- loader -------
    auto load_tile = [&](int k0) {
#pragma unroll
        for (int i = 0; i < 2; i++) {
            int idx = tid + i * 256;
            int row = idx >> 2, c4 = idx & 3;
            float4 vv = *reinterpret_cast<const float4*>(
                A + (size_t)(m0 + row) * lda + k0 + c4 * 4);
            if (BIASA) {
                int kk = k0 + c4 * 4;
                vv.x += biasA[kk]; vv.y += biasA[kk + 1];
                vv.z += biasA[kk + 2]; vv.w += biasA[kk + 3];
            }
            aReg[i] = vv;
        }
        if (TRANSB == 0) {
            if (NPAIRS == 256) {
                int k2 = tid >> 5, n4 = tid & 31;
                bReg[0] = *reinterpret_cast<const float4*>(
                    B + (size_t)(k0 + 2 * k2) * ldb + n0 + n4 * 4);
                bReg[1] = *reinterpret_cast<const float4*>(
                    B + (size_t)(k0 + 2 * k2 + 1) * ldb + n0 + n4 * 4);
            } else {                       // NPAIRS == 128
                if (tid < 128) {
                    int k2 = tid >> 4, n4 = tid & 15;
                    bReg[0] = *reinterpret_cast<const float4*>(
                        B + (size_t)(k0 + 2 * k2) * ldb + n0 + n4 * 4);
                    bReg[1] = *reinterpret_cast<const float4*>(
                        B + (size_t)(k0 + 2 * k2 + 1) * ldb + n0 + n4 * 4);
                }
            }
        } else {
#pragma unroll
            for (int i = 0; i < 2; i++) {
                int idx = tid + i * 256;
                int n = idx >> 2, c4 = idx & 3;
                bReg[i] = *reinterpret_cast<const float4*>(
                    B + (size_t)(n0 + n) * ldb + k0 + c4 * 4);
            }
        }
    };

    // ------- smem store (convert + swizzle) -------
    auto store_tile = [&](int buf) {
#pragma unroll
        for (int i = 0; i < 2; i++) {
            int idx = tid + i * 256;
            int row = idx >> 2, c4 = idx & 3;
            int k2a = 2 * c4, k2b = 2 * c4 + 1;
            uint32_t h0, l0, h1, l1;
            splitpack(aReg[i].x, aReg[i].y, h0, l0);
            splitpack(aReg[i].z, aReg[i].w, h1, l1);
            int ra = row ^ mskA(k2a), rb = row ^ mskA(k2b);
            Ah[buf][k2a * BM + ra] = h0;  Al[buf][k2a * BM + ra] = l0;
            Ah[buf][k2b * BM + rb] = h1;  Al[buf][k2b * BM + rb] = l1;
        }
        if (TRANSB == 0) {
            int k2 = -1, n4 = 0;
            if (NPAIRS == 256)      { k2 = tid >> 5; n4 = tid & 31; }
            else if (tid < 128)     { k2 = tid >> 4; n4 = tid & 15; }
            if (k2 >= 0) {
                uint4 H, L;
                splitpack(bReg[0].x, bReg[1].x, H.x, L.x);
                splitpack(bReg[0].y, bReg[1].y, H.y, L.y);
                splitpack(bReg[0].z, bReg[1].z, H.z, L.z);
                splitpack(bReg[0].w, bReg[1].w, H.w, L.w);
                int base = k2 * BN + ((n4 * 4) ^ mskB(k2));
                *reinterpret_cast<uint4*>(&Bh[buf][base]) = H;
                *reinterpret_cast<uint4*>(&Bl[buf][base]) = L;
            }
        } else {
#pragma unroll
            for (int i = 0; i < 2; i++) {
                int idx = tid + i * 256;
                int n = idx >> 2, c4 = idx & 3;
                int k2a = 2 * c4, k2b = 2 * c4 + 1;
                uint32_t h0, l0, h1, l1;
                splitpack(bReg[i].x, bReg[i].y, h0, l0);
                splitpack(bReg[i].z, bReg[i].w, h1, l1);
                Bh[buf][k2a * BN + (n ^ mskB(k2a))] = h0;
                Bl[buf][k2a * BN + (n ^ mskB(k2a))] = l0;
                Bh[buf][k2b * BN + (n ^ mskB(k2b))] = h1;
                Bl[buf][k2b * BN + (n ^ mskB(k2b))] = l1;
            }
        }
    };

    // ------- pipelined main loop: one sync per K-tile -------
    const int ntiles = K / BK;
    load_tile(0);
    int buf = 0;
    for (int t = 0; t < ntiles; ++t) {
        store_tile(buf);
        __syncthreads();
        if (t + 1 < ntiles) load_tile((t + 1) * BK);

        // fragment loads
        const int mskt  = tig << 3;          // mskA(tig), tig<4
        const int mskt4 = (tig << 3) ^ 1;    // mskA(tig+4)
        const int mskbt  = tig << 3;         // mskB(tig)
        const int mskbt4 = tig << 3;         // mskB(tig+4)
        uint32_t ah[MF][4], al[MF][4], bh[NF][2], bl[NF][2];
#pragma unroll
        for (int mf = 0; mf < MF; mf++) {
            int m = mBase + mf * 16 + gid;
            ah[mf][0] = Ah[buf][ tig      * BM + ( m      ^ mskt )];
            ah[mf][1] = Ah[buf][ tig      * BM + ((m + 8) ^ mskt )];
            ah[mf][2] = Ah[buf][(tig + 4) * BM + ( m      ^ mskt4)];
            ah[mf][3] = Ah[buf][(tig + 4) * BM + ((m + 8) ^ mskt4)];
            al[mf][0] = Al[buf][ tig      * BM + ( m      ^ mskt )];
            al[mf][1] = Al[buf][ tig      * BM + ((m + 8) ^ mskt )];
            al[mf][2] = Al[buf][(tig + 4) * BM + ( m      ^ mskt4)];
            al[mf][3] = Al[buf][(tig + 4) * BM + ((m + 8) ^ mskt4)];
        }
#pragma unroll
        for (int nf = 0; nf < NF; nf++) {
            int n = nBase + nf * 8 + gid;
            bh[nf][0] = Bh[buf][ tig      * BN + (n ^ mskbt )];
            bh[nf][1] = Bh[buf][(tig + 4) * BN + (n ^ mskbt4)];
            bl[nf][0] = Bl[buf][ tig      * BN + (n ^ mskbt )];
            bl[nf][1] = Bl[buf][(tig + 4) * BN + (n ^ mskbt4)];
        }
#pragma unroll
        for (int mf = 0; mf < MF; mf++)
#pragma unroll
            for (int nf = 0; nf < NF; nf++) {
                mma16(acc[mf][nf], ah[mf], bh[nf]);
                mma16(acc[mf][nf], ah[mf], bl[nf]);
                mma16(acc[mf][nf], al[mf], bh[nf]);
            }
        buf ^= 1;
    }

    // ------- epilogue -------
#pragma unroll
    for (int mf = 0; mf < MF; mf++) {
#pragma unroll
        for (int nf = 0; nf < NF; nf++) {
#pragma unroll
            for (int r = 0; r < 4; r++) {
                int m = m0 + mBase + mf * 16 + gid + ((r & 2) ? 8 : 0);
                int n = n0 + nBase + nf * 8 + tig * 2 + (r & 1);
                float v = acc[mf][nf][r];
                if (EPI == 2 || EPI == 3) v += biasC[n];
                if (EPI == 2) v = gelu_exact(v);
                if (EPI == 1 || EPI == 3) v += resC[(size_t)m * ldc + n];
                C[(size_t)m * ldc + n] = v;
            }
        }
    }
}

// ------------------------------ wrappers -----------------------------------
template<int EPI>
__global__ __launch_bounds__(256) void gemm_plain(
    const float* __restrict__ A, const float* __restrict__ B, float* __restrict__ C,
    int K, int lda, int ldb, int ldc,
    const float* __restrict__ biasC, const float* __restrict__ resC)
{
    mm_core<128, 4, 4, 0, EPI, false>(A, B, C, K, lda, ldb, ldc, nullptr, biasC, resC);
}

template<int PER_BATCH>
__global__ __launch_bounds__(256) void score_mma(
    const float* __restrict__ q, const float* __restrict__ kr,
    const float* __restrict__ bias, float* __restrict__ out)
{
    int bh = blockIdx.z, b = bh >> 4, h = bh & 15;
    const float* Ab = q + ((size_t)b * NT) * ND + h * NDH;
    const float* Bb = kr + (PER_BATCH ? ((size_t)b * NL) * ND : (size_t)0) + h * NDH;
    float* Cb = out + (size_t)bh * NT * NL;
    mm_core<128, 4, 4, 1, 0, true>(Ab, Bb, Cb, NDH, ND, ND, NL,
                                   bias + h * NDH, nullptr, nullptr);
}

__global__ __launch_bounds__(256) void attnv_mma(
    const float* __restrict__ attn, const float* __restrict__ v, float* __restrict__ ctx)
{
    int bh = blockIdx.z, b = bh >> 4, h = bh & 15;
    const float* Ab = attn + (size_t)bh * NT * NL;
    const float* Bb = v + ((size_t)b * NL) * ND + h * NDH;
    float* Cb = ctx + ((size_t)b * NT) * ND + h * NDH;
    mm_core<64, 2, 4, 0, 0, false>(Ab, Bb, Cb, NL, NL, ND, ND,
                                   nullptr, nullptr, nullptr);
}

// ------------------- softmax((content + shift(rel)) * scale) ---------------
__global__ void softmax_kernel(float* __restrict__ scores, const float* __restrict__ rel) {
    int row = blockIdx.x;                  // (b*H+h)*T + i
    int i = row & (NT - 1);
    int bh = row >> 10;
    float* srow = scores + (size_t)row * NL;
    const float* relbase = rel + (size_t)bh * NT * NL;
    int tid = threadIdx.x;

    float vals[8];
    float mx = -1e30f;
#pragma unroll
    for (int t = 0; t < 8; t++) {
        int j = tid + t * 256;
        long flat = (long)NT + (long)i * NL + j;
        int p  = (int)(flat / (NL + 1));
        int qq = (int)(flat % (NL + 1));
        float rl = (qq == 0) ? 0.f : relbase[(size_t)p * NL + (qq - 1)];
        float v = (srow[j] + rl) * 0.125f;
        vals[t] = v;
        mx = fmaxf(mx, v);
    }
    __shared__ float red[256];
    red[tid] = mx; __syncthreads();
    for (int o = 128; o > 0; o >>= 1) { if (tid < o) red[tid] = fmaxf(red[tid], red[tid + o]); __syncthreads(); }
    mx = red[0]; __syncthreads();
    float sum = 0.f;
#pragma unroll
    for (int t = 0; t < 8; t++) { vals[t] = expf(vals[t] - mx); sum += vals[t]; }
    red[tid] = sum; __syncthreads();
    for (int o = 128; o > 0; o >>= 1) { if (tid < o) red[tid] += red[tid + o]; __syncthreads(); }
    float inv = 1.0f / red[0];
#pragma unroll
    for (int t = 0; t < 8; t++) srow[tid + t * 256] = vals[t] * inv;
}

// ------------------------------ launch -------------------------------------
extern "C" void kernel_launch(void* const* d_in, const int* in_sizes, int n_in,
                              void* d_out, int out_size) {
    const float* x      = (const float*)d_in[0];
    const float* mem    = (const float*)d_in[1];
    const float* Wq     = (const float*)d_in[2];
    const float* Wk     = (const float*)d_in[3];
    const float* Wv     = (const float*)d_in[4];
    const float* Wr     = (const float*)d_in[5];
    const float* Wo     = (const float*)d_in[6];
    const float* bias_u = (const float*)d_in[7];
    const float* bias_v = (const float*)d_in[8];
    const float* ln1_g  = (const float*)d_in[9];
    const float* ln1_b  = (const float*)d_in[10];
    const float* ln2_g  = (const float*)d_in[11];
    const float* ln2_b  = (const float*)d_in[12];
    const float* W1     = (const float*)d_in[13];
    const float* b1     = (const float*)d_in[14];
    const float* W2     = (const float*)d_in[15];
    const float* b2     = (const float*)d_in[16];
    float* out = (float*)d_out;

    float *xn, *cat, *q, *k, *v, *pe, *r, *scores, *rel, *ctx, *x2, *xf, *ffh;
    cudaGetSymbolAddress((void**)&xn,     g_xn);
    cudaGetSymbolAddress((void**)&cat,    g_cat);
    cudaGetSymbolAddress((void**)&q,      g_q);
    cudaGetSymbolAddress((void**)&k,      g_k);
    cudaGetSymbolAddress((void**)&v,      g_v);
    cudaGetSymbolAddress((void**)&pe,     g_pe);
    cudaGetSymbolAddress((void**)&r,      g_r);
    cudaGetSymbolAddress((void**)&scores, g_scores);
    cudaGetSymbolAddress((void**)&rel,    g_rel);
    cudaGetSymbolAddress((void**)&ctx,    g_ctx);
    cudaGetSymbolAddress((void**)&x2,     g_x2);
    cudaGetSymbolAddress((void**)&xf,     g_xf);
    cudaGetSymbolAddress((void**)&ffh,    g_ffh);

    pe_kernel<<<(NL * ND + 255) / 256, 256>>>(pe);
    ln_kernel<<<NB * NT, 256>>>(x, ln1_g, ln1_b, xn);
    cat_kernel<<<(unsigned)((BLD + 255) / 256), 256>>>(mem, xn, cat);

    // projections
    gemm_plain<0><<<dim3(ND / 128,   (NB * NT) / 128), 256>>>(xn,  Wq, q, ND, ND, ND, ND, nullptr, nullptr);
    gemm_plain<0><<<dim3(ND / 128,   (NB * NL) / 128), 256>>>(cat, Wk, k, ND, ND, ND, ND, nullptr, nullptr);
    gemm_plain<0><<<dim3(ND / 128,   (NB * NL) / 128), 256>>>(cat, Wv, v, ND, ND, ND, ND, nullptr, nullptr);
    gemm_plain<0><<<dim3(ND / 128,   NL / 128),        256>>>(pe,  Wr, r, ND, ND, ND, ND, nullptr, nullptr);

    // attention logits
    score_mma<1><<<dim3(NL / 128, NT / 128, NB * NH), 256>>>(q, k, bias_u, scores);
    score_mma<0><<<dim3(NL / 128, NT / 128, NB * NH), 256>>>(q, r, bias_v, rel);

    // softmax with fused rel-shift
    softmax_kernel<<<NB * NH * NT, 256>>>(scores, rel);

    // context
    attnv_mma<<<dim3(1, NT / 128, NB * NH), 256>>>(scores, v, ctx);

    // output proj + residual
    gemm_plain<1><<<dim3(ND / 128, (NB * NT) / 128), 256>>>(ctx, Wo, x2, ND, ND, ND, ND, nullptr, x);

    ln_kernel<<<NB * NT, 256>>>(x2, ln2_g, ln2_b, xf);

    // FFN
    gemm_plain<2><<<dim3(NDFF / 128, (NB * NT) / 128), 256>>>(xf,  W1, ffh, ND,   ND,   NDFF, NDFF, b1, nullptr);
    gemm_plain<3><<<dim3(ND / 128,   (NB * NT) / 128), 256>>>(ffh, W2, out, NDFF, NDFF, ND,   ND,   b2, x2);

    // new_mem = x
    if ((size_t)out_size >= 2 * BTD) {
        cudaMemcpyAsync(out + BTD, x, BTD * sizeof(float), cudaMemcpyDeviceToDevice);
    }
}

// round 6
// speedup vs baseline: 3.1055x; 1.1156x over previous
#include <cuda_runtime.h>
#include <cuda_bf16.h>
#include <math.h>
#include <stdint.h>

// ---------------------------------------------------------------------------
// Transformer-XL block. Split-bf16 tensor-core GEMMs + flash-fused attention.
//   fp32 value = hi(bf16) + lo(bf16);  A*B ~= Ah*Bh + Ah*Bl + Al*Bh
//   B=4, T=1024, M=1024, D=1024, H=16, dh=64, L=2048, Dff=4096
// Outputs: y [B,T,D] then new_mem [B,1024,D] == x.
// ---------------------------------------------------------------------------

#define NB   4
#define NT   1024
#define NM   1024
#define ND   1024
#define NH   16
#define NDH  64
#define NL   2048
#define NDFF 4096

#define BTD  ((size_t)NB * NT * ND)
#define BLD  ((size_t)NB * NL * ND)
#define SCSZ ((size_t)NB * NH * NT * NL)

// -------------------------- scratch (device globals) -----------------------
__device__ float g_xn [BTD];
__device__ float g_cat[BLD];
__device__ float g_q  [BTD];
__device__ float g_k  [BLD];
__device__ float g_v  [BLD];
__device__ float g_pe [(size_t)NL * ND];
__device__ float g_r  [(size_t)NL * ND];
__device__ float g_rel[SCSZ];              // raw rel logits D[bh][T][L]
__device__ float g_ctx[BTD];
__device__ float g_x2 [BTD];
__device__ float g_xf [BTD];
__device__ float g_ffh[(size_t)NB * NT * NDFF];

// ------------------------------ helpers ------------------------------------
__device__ __forceinline__ float gelu_exact(float v) {
    return 0.5f * v * (1.0f + erff(v * 0.70710678118654752f));
}

// Pack (x -> low16, y -> high16) as bf16x2 hi, and the bf16x2 of residuals.
__device__ __forceinline__ void splitpack(float x, float y, uint32_t& hi, uint32_t& lo) {
    uint32_t h;
    asm("cvt.rn.bf16x2.f32 %0, %1, %2;" : "=r"(h) : "f"(y), "f"(x));
    float hx = __uint_as_float(h << 16);
    float hy = __uint_as_float(h & 0xFFFF0000u);
    uint32_t l;
    asm("cvt.rn.bf16x2.f32 %0, %1, %2;" : "=r"(l) : "f"(y - hy), "f"(x - hx));
    hi = h; lo = l;
}

__device__ __forceinline__ void mma16(float* c, const uint32_t* a, const uint32_t* b) {
    asm volatile("mma.sync.aligned.m16n8k16.row.col.f32.bf16.bf16.f32 "
        "{%0,%1,%2,%3}, {%4,%5,%6,%7}, {%8,%9}, {%0,%1,%2,%3};\n"
        : "+f"(c[0]), "+f"(c[1]), "+f"(c[2]), "+f"(c[3])
        : "r"(a[0]), "r"(a[1]), "r"(a[2]), "r"(a[3]), "r"(b[0]), "r"(b[1]));
}

__device__ __forceinline__ int mskA(int k2) { return ((k2 & 3) << 3) ^ (k2 >> 2); }
__device__ __forceinline__ int mskB(int k2) { return (k2 & 3) << 3; }

// ------------------------------ pos emb ------------------------------------
__global__ void pe_kernel(float* __restrict__ pe) {
    int idx = blockIdx.x * blockDim.x + threadIdx.x;
    if (idx >= NL * ND) return;
    int l = idx / ND, d = idx % ND;
    float pos = (float)(NL - 1 - l);
    int j = (d < ND / 2) ? d : d - ND / 2;
    float invf = powf(10000.0f, -(2.0f * (float)j) / (float)ND);
    float a = pos * invf;
    pe[idx] = (d < ND / 2) ? sinf(a) : cosf(a);
}

// ------------------------------ layer norm ---------------------------------
__global__ void ln_kernel(const float* __restrict__ x, const float* __restrict__ g,
                          const float* __restrict__ b, float* __restrict__ out) {
    int row = blockIdx.x;
    const float* xr = x + (size_t)row * ND;
    int tid = threadIdx.x;
    float v[4];
    float s = 0.f;
#pragma unroll
    for (int i = 0; i < 4; i++) { v[i] = xr[tid + i * 256]; s += v[i]; }
    __shared__ float red[256];
    red[tid] = s; __syncthreads();
    for (int o = 128; o > 0; o >>= 1) { if (tid < o) red[tid] += red[tid + o]; __syncthreads(); }
    float mu = red[0] * (1.0f / ND);
    __syncthreads();
    float s2 = 0.f;
#pragma unroll
    for (int i = 0; i < 4; i++) { float t = v[i] - mu; s2 += t * t; }
    red[tid] = s2; __syncthreads();
    for (int o = 128; o > 0; o >>= 1) { if (tid < o) red[tid] += red[tid + o]; __syncthreads(); }
    float rstd = rsqrtf(red[0] * (1.0f / ND) + 1e-5f);
    float* orow = out + (size_t)row * ND;
#pragma unroll
    for (int i = 0; i < 4; i++) {
        int c = tid + i * 256;
        orow[c] = (v[i] - mu) * rstd * g[c] + b[c];
    }
}

// ------------------------- cat = [mem ; xn] --------------------------------
__global__ void cat_kernel(const float* __restrict__ mem, const float* __restrict__ xn,
                           float* __restrict__ cat) {
    size_t idx = (size_t)blockIdx.x * blockDim.x + threadIdx.x;
    if (idx >= BLD) return;
    size_t b = idx / ((size_t)NL * ND);
    size_t rem = idx - b * (size_t)NL * ND;
    int l = (int)(rem / ND);
    int d = (int)(rem % ND);
    float val;
    if (l < NM) val = mem[(b * NM + l) * ND + d];
    else        val = xn [(b * NT + (l - NM)) * ND + d];
    cat[idx] = val;
}

// ------------------- split-bf16 mma GEMM core (pipelined) ------------------
template<int BN, int MF, int NF, int TRANSB, int EPI, bool BIASA>
__device__ __forceinline__ void mm_core(
    const float* __restrict__ A, const float* __restrict__ B, float* __restrict__ C,
    int K, int lda, int ldb, int ldc,
    const float* __restrict__ biasA, const float* __restrict__ biasC,
    const float* __restrict__ resC)
{
    constexpr int BM = 128, BK = 16, BK2 = 8;
    __shared__ __align__(16) uint32_t Ah[2][BK2 * BM];
    __shared__ __align__(16) uint32_t Al[2][BK2 * BM];
    __shared__ __align__(16) uint32_t Bh[2][BK2 * BN];
    __shared__ __align__(16) uint32_t Bl[2][BK2 * BN];

    const int tid  = threadIdx.x;
    const int lane = tid & 31;
    const int w    = tid >> 5;
    constexpr int WARPS_M = BM / (MF * 16);
    const int wm = w % WARPS_M;
    const int wn = w / WARPS_M;
    const int mBase = wm * MF * 16;
    const int nBase = wn * NF * 8;
    const int m0 = blockIdx.y * BM;
    const int n0 = blockIdx.x * BN;
    const int tig = lane & 3;
    const int gid = lane >> 2;

    float acc[MF][NF][4];
#pragma unroll
    for (int i = 0; i < MF; i++)
#pragma unroll
        for (int j = 0; j < NF; j++)
#pragma unroll
            for (int r = 0; r < 4; r++) acc[i][j][r] = 0.f;

    float4 aReg[2];
    float4 bReg[2];
    constexpr int NPAIRS = 2 * BN;

    auto load_tile = [&](int k0) {
#pragma unroll
        for (int i = 0; i < 2; i++) {
            int idx = tid + i * 256;
            int row = idx >> 2, c4 = idx & 3;
            float4 vv = *reinterpret_cast<const float4*>(
                A + (size_t)(m0 + row) * lda + k0 + c4 * 4);
            if (BIASA) {
                int kk = k0 + c4 * 4;
                vv.x += biasA[kk]; vv.y += biasA[kk + 1];
                vv.z += biasA[kk + 2]; vv.w += biasA[kk + 3];
            }
            aReg[i] = vv;
        }
        if (TRANSB == 0) {
            if (NPAIRS == 256) {
                int k2 = tid >> 5, n4 = tid & 31;
                bReg[0] = *reinterpret_cast<const float4*>(
                    B + (size_t)(k0 + 2 * k2) * ldb + n0 + n4 * 4);
                bReg[1] = *reinterpret_cast<const float4*>(
                    B + (size_t)(k0 + 2 * k2 + 1) * ldb + n0 + n4 * 4);
            } else {
                if (tid < 128) {
                    int k2 = tid >> 4, n4 = tid & 15;
                    bReg[0] = *reinterpret_cast<const float4*>(
                        B + (size_t)(k0 + 2 * k2) * ldb + n0 + n4 * 4);
                    bReg[1] = *reinterpret_cast<const float4*>(
                        B + (size_t)(k0 + 2 * k2 + 1) * ldb + n0 + n4 * 4);
                }
            }
        } else {
#pragma unroll
            for (int i = 0; i < 2; i++) {
                int idx = tid + i * 256;
                int n = idx >> 2, c4 = idx & 3;
                bReg[i] = *reinterpret_cast<const float4*>(
                    B + (size_t)(n0 + n) * ldb + k0 + c4 * 4);
            }
        }
    };

    auto store_tile = [&](int buf) {
#pragma unroll
        for (int i = 0; i < 2; i++) {
            int idx = tid + i * 256;
            int row = idx >> 2, c4 = idx & 3;
            int k2a = 2 * c4, k2b = 2 * c4 + 1;
            uint32_t h0, l0, h1, l1;
            splitpack(aReg[i].x, aReg[i].y, h0, l0);
            splitpack(aReg[i].z, aReg[i].w, h1, l1);
            int ra = row ^ mskA(k2a), rb = row ^ mskA(k2b);
            Ah[buf][k2a * BM + ra] = h0;  Al[buf][k2a * BM + ra] = l0;
            Ah[buf][k2b * BM + rb] = h1;  Al[buf][k2b * BM + rb] = l1;
        }
        if (TRANSB == 0) {
            int k2 = -1, n4 = 0;
            if (NPAIRS == 256)      { k2 = tid >> 5; n4 = tid & 31; }
            else if (tid < 128)     { k2 = tid >> 4; n4 = tid & 15; }
            if (k2 >= 0) {
                uint4 H, L;
                splitpack(bReg[0].x, bReg[1].x, H.x, L.x);
                splitpack(bReg[0].y, bReg[1].y, H.y, L.y);
                splitpack(bReg[0].z, bReg[1].z, H.z, L.z);
                splitpack(bReg[0].w, bReg[1].w, H.w, L.w);
                int base = k2 * BN + ((n4 * 4) ^ mskB(k2));
                *reinterpret_cast<uint4*>(&Bh[buf][base]) = H;
                *reinterpret_cast<uint4*>(&Bl[buf][base]) = L;
            }
        } else {
#pragma unroll
            for (int i = 0; i < 2; i++) {
                int idx = tid + i * 256;
                int n = idx >> 2, c4 = idx & 3;
                int k2a = 2 * c4, k2b = 2 * c4 + 1;
                uint32_t h0, l0, h1, l1;
                splitpack(bReg[i].x, bReg[i].y, h0, l0);
                splitpack(bReg[i].z, bReg[i].w, h1, l1);
                Bh[buf][k2a * BN + (n ^ mskB(k2a))] = h0;
                Bl[buf][k2a * BN + (n ^ mskB(k2a))] = l0;
                Bh[buf][k2b * BN + (n ^ mskB(k2b))] = h1;
                Bl[buf][k2b * BN + (n ^ mskB(k2b))] = l1;
            }
        }
    };

    const int ntiles = K / BK;
    load_tile(0);
    int buf = 0;
    for (int t = 0; t < ntiles; ++t) {
        store_tile(buf);
        __syncthreads();
        if (t + 1 < ntiles) load_tile((t + 1) * BK);

        const int mskt  = tig << 3;
        const int mskt4 = (tig << 3) ^ 1;
        const int mskbt  = tig << 3;
        const int mskbt4 = tig << 3;
        uint32_t ah[MF][4], al[MF][4], bh[NF][2], bl[NF][2];
#pragma unroll
        for (int mf = 0; mf < MF; mf++) {
            int m = mBase + mf * 16 + gid;
            ah[mf][0] = Ah[buf][ tig      * BM + ( m      ^ mskt )];
            ah[mf][1] = Ah[buf][ tig      * BM + ((m + 8) ^ mskt )];
            ah[mf][2] = Ah[buf][(tig + 4) * BM + ( m      ^ mskt4)];
            ah[mf][3] = Ah[buf][(tig + 4) * BM + ((m + 8) ^ mskt4)];
            al[mf][0] = Al[buf][ tig      * BM + ( m      ^ mskt )];
            al[mf][1] = Al[buf][ tig      * BM + ((m + 8) ^ mskt )];
            al[mf][2] = Al[buf][(tig + 4) * BM + ( m      ^ mskt4)];
            al[mf][3] = Al[buf][(tig + 4) * BM + ((m + 8) ^ mskt4)];
        }
#pragma unroll
        for (int nf = 0; nf < NF; nf++) {
            int n = nBase + nf * 8 + gid;
            bh[nf][0] = Bh[buf][ tig      * BN + (n ^ mskbt )];
            bh[nf][1] = Bh[buf][(tig + 4) * BN + (n ^ mskbt4)];
            bl[nf][0] = Bl[buf][ tig      * BN + (n ^ mskbt )];
            bl[nf][1] = Bl[buf][(tig + 4) * BN + (n ^ mskbt4)];
        }
#pragma unroll
        for (int mf = 0; mf < MF; mf++)
#pragma unroll
            for (int nf = 0; nf < NF; nf++) {
                mma16(acc[mf][nf], ah[mf], bh[nf]);
                mma16(acc[mf][nf], ah[mf], bl[nf]);
                mma16(acc[mf][nf], al[mf], bh[nf]);
            }
        buf ^= 1;
    }

#pragma unroll
    for (int mf = 0; mf < MF; mf++) {
#pragma unroll
        for (int nf = 0; nf < NF; nf++) {
#pragma unroll
            for (int r = 0; r < 4; r++) {
                int m = m0 + mBase + mf * 16 + gid + ((r & 2) ? 8 : 0);
                int n = n0 + nBase + nf * 8 + tig * 2 + (r & 1);
                float v = acc[mf][nf][r];
                if (EPI == 2 || EPI == 3) v += biasC[n];
                if (EPI == 2) v = gelu_exact(v);
                if (EPI == 1 || EPI == 3) v += resC[(size_t)m * ldc + n];
                C[(size_t)m * ldc + n] = v;
            }
        }
    }
}

// ------------------------------ wrappers -----------------------------------
template<int EPI>
__global__ __launch_bounds__(256) void gemm_plain(
    const float* __restrict__ A, const float* __restrict__ B, float* __restrict__ C,
    int K, int lda, int ldb, int ldc,
    const float* __restrict__ biasC, const float* __restrict__ resC)
{
    mm_core<128, 4, 4, 0, EPI, false>(A, B, C, K, lda, ldb, ldc, nullptr, biasC, resC);
}

// raw rel logits: D[bh][i][l] = (q_i + bias_v) . r_l
__global__ __launch_bounds__(256) void relraw_mma(
    const float* __restrict__ q, const float* __restrict__ r,
    const float* __restrict__ bias, float* __restrict__ out)
{
    int bh = blockIdx.z, b = bh >> 4, h = bh & 15;
    const float* Ab = q + ((size_t)b * NT) * ND + h * NDH;
    const float* Bb = r + h * NDH;
    float* Cb = out + (size_t)bh * NT * NL;
    mm_core<128, 4, 4, 1, 0, true>(Ab, Bb, Cb, NDH, ND, ND, NL,
                                   bias + h * NDH, nullptr, nullptr);
}

// -------------------- flash-fused attention ---------------------------------
// Per (bh, 128-row i-tile): S = (Q+bu)K^T computed by split-bf16 mma;
// shifted rel gathered from raw D; online softmax; P.V accumulated with the
// in-register fragment repack. ctx written fp32.
__global__ __launch_bounds__(256) void flash_kernel(
    const float* __restrict__ qg, const float* __restrict__ kg,
    const float* __restrict__ vg, const float* __restrict__ Dg,
    const float* __restrict__ bias_u, float* __restrict__ ctx)
{
    extern __shared__ uint32_t smx[];
    uint32_t* Qh = smx;           uint32_t* Ql = smx + 4096;
    uint32_t* Kh = smx + 8192;    uint32_t* Kl = smx + 12288;
    uint32_t* Vh = smx + 16384;   uint32_t* Vl = smx + 20480;

    const int tid = threadIdx.x, lane = tid & 31, w = tid >> 5;
    const int gid = lane >> 2, tig = lane & 3;
    const int bh = blockIdx.y, b = bh >> 4, hd = bh & 15;
    const int i0 = blockIdx.x * 128;

    const float* qb = qg + (size_t)(b * NT + i0) * ND + hd * NDH;
    const float* kb = kg + (size_t)b * NL * ND + hd * NDH;
    const float* vb = vg + (size_t)b * NL * ND + hd * NDH;
    const float* Db = Dg + (size_t)bh * NT * NL;
    float*       cb = ctx + (size_t)(b * NT + i0) * ND + hd * NDH;
    const float* bu = bias_u + hd * NDH;

    // ---- load Q (once), +bias_u, split-pack, swizzle ----
#pragma unroll
    for (int it = 0; it < 8; it++) {
        int idx = tid + it * 256;
        int row = idx >> 4, c4 = idx & 15;
        float4 t = *reinterpret_cast<const float4*>(qb + (size_t)row * ND + c4 * 4);
        t.x += bu[c4 * 4]; t.y += bu[c4 * 4 + 1]; t.z += bu[c4 * 4 + 2]; t.w += bu[c4 * 4 + 3];
        int k2a = 2 * c4, k2b = 2 * c4 + 1;
        uint32_t h0, l0, h1, l1;
        splitpack(t.x, t.y, h0, l0);
        splitpack(t.z, t.w, h1, l1);
        Qh[k2a * 128 + (row ^ mskA(k2a))] = h0; Ql[k2a * 128 + (row ^ mskA(k2a))] = l0;
        Qh[k2b * 128 + (row ^ mskA(k2b))] = h1; Ql[k2b * 128 + (row ^ mskA(k2b))] = l1;
    }

    const int mBase = w * 16;
    const int iA = i0 + mBase + gid;                 // global query row (r0,r1)
    const float* DrowA = Db + (size_t)iA * NL;
    const float* DrowB = DrowA + (size_t)8 * NL;     // row iA+8

    float mA = -1e30f, mB = -1e30f, lA = 0.f, lB = 0.f;
    float oacc[8][4];
#pragma unroll
    for (int i = 0; i < 8; i++)
#pragma unroll
        for (int r = 0; r < 4; r++) oacc[i][r] = 0.f;

    for (int jt = 0; jt < NL / 128; jt++) {
        const int j0 = jt * 128;
        __syncthreads();    // previous tile fully consumed (also orders Q stores on jt=0)

        // ---- K tile: 128 x 64, packed along d ----
#pragma unroll
        for (int it = 0; it < 8; it++) {
            int idx = tid + it * 256;
            int row = idx >> 4, c4 = idx & 15;
            float4 t = *reinterpret_cast<const float4*>(kb + (size_t)(j0 + row) * ND + c4 * 4);
            int k2a = 2 * c4, k2b = 2 * c4 + 1;
            uint32_t h0, l0, h1, l1;
            splitpack(t.x, t.y, h0, l0);
            splitpack(t.z, t.w, h1, l1);
            Kh[k2a * 128 + (row ^ mskA(k2a))] = h0; Kl[k2a * 128 + (row ^ mskA(k2a))] = l0;
            Kh[k2b * 128 + (row ^ mskA(k2b))] = h1; Kl[k2b * 128 + (row ^ mskA(k2b))] = l1;
        }
        // ---- V tile: 128 x 64, packed along j (PV K-dim) ----
#pragma unroll
        for (int it = 0; it < 4; it++) {
            int idx = tid + it * 256;
            int k2 = idx >> 4, n4 = idx & 15;
            const float* p0 = vb + (size_t)(j0 + 2 * k2) * ND + n4 * 4;
            float4 v0 = *reinterpret_cast<const float4*>(p0);
            float4 v1 = *reinterpret_cast<const float4*>(p0 + ND);
            uint4 H, L;
            splitpack(v0.x, v1.x, H.x, L.x);
            splitpack(v0.y, v1.y, H.y, L.y);
            splitpack(v0.z, v1.z, H.z, L.z);
            splitpack(v0.w, v1.w, H.w, L.w);
            int base = k2 * 64 + ((n4 * 4) ^ mskB(k2));
            *reinterpret_cast<uint4*>(Vh + base) = H;
            *reinterpret_cast<uint4*>(Vl + base) = L;
        }
        __syncthreads();

        // ---- QK: S[16 x 128] per warp ----
        float sacc[16][4];
#pragma unroll
        for (int i = 0; i < 16; i++)
#pragma unroll
            for (int r = 0; r < 4; r++) sacc[i][r] = 0.f;

#pragma unroll
        for (int kt = 0; kt < 4; kt++) {
            int k21 = kt * 8 + tig, k22 = k21 + 4;
            int m1 = mskA(k21), m2 = mskA(k22);
            int m = mBase + gid;
            uint32_t ah[4], al[4];
            ah[0] = Qh[k21 * 128 + ( m      ^ m1)];
            ah[1] = Qh[k21 * 128 + ((m + 8) ^ m1)];
            ah[2] = Qh[k22 * 128 + ( m      ^ m2)];
            ah[3] = Qh[k22 * 128 + ((m + 8) ^ m2)];
            al[0] = Ql[k21 * 128 + ( m      ^ m1)];
            al[1] = Ql[k21 * 128 + ((m + 8) ^ m1)];
            al[2] = Ql[k22 * 128 + ( m      ^ m2)];
            al[3] = Ql[k22 * 128 + ((m + 8) ^ m2)];
#pragma unroll
            for (int nf = 0; nf < 16; nf++) {
                int n = nf * 8 + gid;
                uint32_t bhv[2] = { Kh[k21 * 128 + (n ^ m1)], Kh[k22 * 128 + (n ^ m2)] };
                uint32_t blv[2] = { Kl[k21 * 128 + (n ^ m1)], Kl[k22 * 128 + (n ^ m2)] };
                mma16(sacc[nf], ah, bhv);
                mma16(sacc[nf], ah, blv);
                mma16(sacc[nf], al, bhv);
            }
        }

        // ---- add shifted rel (gathered from D), scale, tile row-max ----
        const int jc = j0 + 2 * tig;
        float mAt = -1e30f, mBt = -1e30f;
#pragma unroll
        for (int nf = 0; nf < 16; nf++) {
            int j = jc + nf * 8;
            int d0 = j - iA, d1 = d0 + 1;
            int e0 = d0 - 8, e1 = e0 + 1;
            float D0 = DrowA[d0 + (d0 <= 1024 ? 1023 : 1022)];
            float D1 = DrowA[d1 + (d1 <= 1024 ? 1023 : 1022)];
            float E0 = DrowB[e0 + (e0 <= 1024 ? 1023 : 1022)];
            float E1 = DrowB[e1 + (e1 <= 1024 ? 1023 : 1022)];
            if (d0 == 1025) D0 = 0.f;
            if (d1 == 1025) D1 = 0.f;
            if (e0 == 1025) E0 = 0.f;
            if (e1 == 1025) E1 = 0.f;
            float s0 = (sacc[nf][0] + D0) * 0.125f;
            float s1 = (sacc[nf][1] + D1) * 0.125f;
            float s2 = (sacc[nf][2] + E0) * 0.125f;
            float s3 = (sacc[nf][3] + E1) * 0.125f;
            sacc[nf][0] = s0; sacc[nf][1] = s1; sacc[nf][2] = s2; sacc[nf][3] = s3;
            mAt = fmaxf(mAt, fmaxf(s0, s1));
            mBt = fmaxf(mBt, fmaxf(s2, s3));
        }
        mAt = fmaxf(mAt, __shfl_xor_sync(0xFFFFFFFFu, mAt, 1));
        mAt = fmaxf(mAt, __shfl_xor_sync(0xFFFFFFFFu, mAt, 2));
        mBt = fmaxf(mBt, __shfl_xor_sync(0xFFFFFFFFu, mBt, 1));
        mBt = fmaxf(mBt, __shfl_xor_sync(0xFFFFFFFFu, mBt, 2));

        float mAn = fmaxf(mA, mAt), mBn = fmaxf(mB, mBt);
        float cA = __expf(mA - mAn), cB = __expf(mB - mBn);
        mA = mAn; mB = mBn;
        lA *= cA; lB *= cB;
#pragma unroll
        for (int nfv = 0; nfv < 8; nfv++) {
            oacc[nfv][0] *= cA; oacc[nfv][1] *= cA;
            oacc[nfv][2] *= cB; oacc[nfv][3] *= cB;
        }

        // ---- exp, split-pack P into PV A-fragments (in registers) ----
        uint32_t pah[8][4], pal[8][4];
#pragma unroll
        for (int kt = 0; kt < 8; kt++) {
            float p00 = __expf(sacc[2*kt  ][0] - mA), p01 = __expf(sacc[2*kt  ][1] - mA);
            float p02 = __expf(sacc[2*kt  ][2] - mB), p03 = __expf(sacc[2*kt  ][3] - mB);
            float p10 = __expf(sacc[2*kt+1][0] - mA), p11 = __expf(sacc[2*kt+1][1] - mA);
            float p12 = __expf(sacc[2*kt+1][2] - mB), p13 = __expf(sacc[2*kt+1][3] - mB);
            lA += p00 + p01 + p10 + p11;
            lB += p02 + p03 + p12 + p13;
            splitpack(p00, p01, pah[kt][0], pal[kt][0]);
            splitpack(p02, p03, pah[kt][1], pal[kt][1]);
            splitpack(p10, p11, pah[kt][2], pal[kt][2]);
            splitpack(p12, p13, pah[kt][3], pal[kt][3]);
        }

        // ---- PV: out[16 x 64] per warp, K = 128 (j) ----
#pragma unroll
        for (int kt = 0; kt < 8; kt++) {
            int k21 = kt * 8 + tig, k22 = k21 + 4;
            int mv = tig << 3;
#pragma unroll
            for (int nfv = 0; nfv < 8; nfv++) {
                int n = nfv * 8 + gid;
                uint32_t vbh[2] = { Vh[k21 * 64 + (n ^ mv)], Vh[k22 * 64 + (n ^ mv)] };
                uint32_t vbl[2] = { Vl[k21 * 64 + (n ^ mv)], Vl[k22 * 64 + (n ^ mv)] };
                mma16(oacc[nfv], pah[kt], vbh);
                mma16(oacc[nfv], pah[kt], vbl);
                mma16(oacc[nfv], pal[kt], vbh);
            }
        }
    }

    // ---- finalize: full row sums, normalize, write ctx ----
    lA += __shfl_xor_sync(0xFFFFFFFFu, lA, 1);
    lA += __shfl_xor_sync(0xFFFFFFFFu, lA, 2);
    lB += __shfl_xor_sync(0xFFFFFFFFu, lB, 1);
    lB += __shfl_xor_sync(0xFFFFFFFFu, lB, 2);
    float invA = 1.0f / lA, invB = 1.0f / lB;
    const int rowA = mBase + gid, rowB = rowA + 8;
#pragma unroll
    for (int nfv = 0; nfv < 8; nfv++) {
        int n = nfv * 8 + 2 * tig;
        cb[(size_t)rowA * ND + n]     = oacc[nfv][0] * invA;
        cb[(size_t)rowA * ND + n + 1] = oacc[nfv][1] * invA;
        cb[(size_t)rowB * ND + n]     = oacc[nfv][2] * invB;
        cb[(size_t)rowB * ND + n + 1] = oacc[nfv][3] * invB;
    }
}

#define FLASH_SMEM (24576 * 4)

// ------------------------------ launch -------------------------------------
extern "C" void kernel_launch(void* const* d_in, const int* in_sizes, int n_in,
                              void* d_out, int out_size) {
    const float* x      = (const float*)d_in[0];
    const float* mem    = (const float*)d_in[1];
    const float* Wq     = (const float*)d_in[2];
    const float* Wk     = (const float*)d_in[3];
    const float* Wv     = (const float*)d_in[4];
    const float* Wr     = (const float*)d_in[5];
    const float* Wo     = (const float*)d_in[6];
    const float* bias_u = (const float*)d_in[7];
    const float* bias_v = (const float*)d_in[8];
    const float* ln1_g  = (const float*)d_in[9];
    const float* ln1_b  = (const float*)d_in[10];
    const float* ln2_g  = (const float*)d_in[11];
    const float* ln2_b  = (const float*)d_in[12];
    const float* W1     = (const float*)d_in[13];
    const float* b1     = (const float*)d_in[14];
    const float* W2     = (const float*)d_in[15];
    const float* b2     = (const float*)d_in[16];
    float* out = (float*)d_out;

    float *xn, *cat, *q, *k, *v, *pe, *r, *rel, *ctx, *x2, *xf, *ffh;
    cudaGetSymbolAddress((void**)&xn,  g_xn);
    cudaGetSymbolAddress((void**)&cat, g_cat);
    cudaGetSymbolAddress((void**)&q,   g_q);
    cudaGetSymbolAddress((void**)&k,   g_k);
    cudaGetSymbolAddress((void**)&v,   g_v);
    cudaGetSymbolAddress((void**)&pe,  g_pe);
    cudaGetSymbolAddress((void**)&r,   g_r);
    cudaGetSymbolAddress((void**)&rel, g_rel);
    cudaGetSymbolAddress((void**)&ctx, g_ctx);
    cudaGetSymbolAddress((void**)&x2,  g_x2);
    cudaGetSymbolAddress((void**)&xf,  g_xf);
    cudaGetSymbolAddress((void**)&ffh, g_ffh);

    cudaFuncSetAttribute(flash_kernel,
                         cudaFuncAttributeMaxDynamicSharedMemorySize, FLASH_SMEM);

    pe_kernel<<<(NL * ND + 255) / 256, 256>>>(pe);
    ln_kernel<<<NB * NT, 256>>>(x, ln1_g, ln1_b, xn);
    cat_kernel<<<(unsigned)((BLD + 255) / 256), 256>>>(mem, xn, cat);

    // projections
    gemm_plain<0><<<dim3(ND / 128,   (NB * NT) / 128), 256>>>(xn,  Wq, q, ND, ND, ND, ND, nullptr, nullptr);
    gemm_plain<0><<<dim3(ND / 128,   (NB * NL) / 128), 256>>>(cat, Wk, k, ND, ND, ND, ND, nullptr, nullptr);
    gemm_plain<0><<<dim3(ND / 128,   (NB * NL) / 128), 256>>>(cat, Wv, v, ND, ND, ND, ND, nullptr, nullptr);
    gemm_plain<0><<<dim3(ND / 128,   NL / 128),        256>>>(pe,  Wr, r, ND, ND, ND, ND, nullptr, nullptr);

    // raw rel logits D (consumed with shift inside flash kernel)
    relraw_mma<<<dim3(NL / 128, NT / 128, NB * NH), 256>>>(q, r, bias_v, rel);

    // flash attention: content + shifted rel + softmax + P.V
    flash_kernel<<<dim3(NT / 128, NB * NH), 256, FLASH_SMEM>>>(q, k, v, rel, bias_u, ctx);

    // output proj + residual
    gemm_plain<1><<<dim3(ND / 128, (NB * NT) / 128), 256>>>(ctx, Wo, x2, ND, ND, ND, ND, nullptr, x);

    ln_kernel<<<NB * NT, 256>>>(x2, ln2_g, ln2_b, xf);

    // FFN
    gemm_plain<2><<<dim3(NDFF / 128, (NB * NT) / 128), 256>>>(xf,  W1, ffh, ND,   ND,   NDFF, NDFF, b1, nullptr);
    gemm_plain<3><<<dim3(ND / 128,   (NB * NT) / 128), 256>>>(ffh, W2, out, NDFF, NDFF, ND,   ND,   b2, x2);

    // new_mem = x
    if ((size_t)out_size >= 2 * BTD) {
        cudaMemcpyAsync(out + BTD, x, BTD * sizeof(float), cudaMemcpyDeviceToDevice);
    }
}

// round 7
// speedup vs baseline: 3.2882x; 1.0588x over previous
#include <cuda_runtime.h>
#include <cuda_bf16.h>
#include <math.h>
#include <stdint.h>

// ---------------------------------------------------------------------------
// Transformer-XL block. All GEMM operands pre-split into packed bf16x2
// hi/lo planes; GEMM mainloop = cp.async 3-stage pipeline + split-bf16 mma
// (Ah*Bh + Ah*Bl + Al*Bh). Flash-fused attention.
//   B=4, T=1024, M=1024, D=1024, H=16, dh=64, L=2048, Dff=4096
// Outputs: y [B,T,D] then new_mem [B,1024,D] == x.
// ---------------------------------------------------------------------------

#define NB   4
#define NT   1024
#define NM   1024
#define ND   1024
#define NH   16
#define NDH  64
#define NL   2048
#define NDFF 4096

#define BTD  ((size_t)NB * NT * ND)
#define SCSZ ((size_t)NB * NH * NT * NL)

// ---------------- packed bf16x2 planes (u32) + fp32 scratch ----------------
__device__ uint32_t g_xnh [BTD/2],  g_xnl [BTD/2];
__device__ uint32_t g_cath[(size_t)NB*NL*ND/2], g_catl[(size_t)NB*NL*ND/2];
__device__ uint32_t g_peh [(size_t)NL*ND/2],    g_pel [(size_t)NL*ND/2];
__device__ uint32_t g_qvh [BTD/2],  g_qvl [BTD/2];
__device__ uint32_t g_rh  [(size_t)NL*ND/2],    g_rl  [(size_t)NL*ND/2];
__device__ uint32_t g_ctxh[BTD/2],  g_ctxl[BTD/2];
__device__ uint32_t g_xfh [BTD/2],  g_xfl [BTD/2];
__device__ uint32_t g_ffhh[(size_t)NB*NT*NDFF/2], g_ffhl[(size_t)NB*NT*NDFF/2];
__device__ uint32_t g_wqh[(size_t)ND*ND/2], g_wql[(size_t)ND*ND/2];
__device__ uint32_t g_wkh[(size_t)ND*ND/2], g_wkl[(size_t)ND*ND/2];
__device__ uint32_t g_wvh[(size_t)ND*ND/2], g_wvl[(size_t)ND*ND/2];
__device__ uint32_t g_wrh[(size_t)ND*ND/2], g_wrl[(size_t)ND*ND/2];
__device__ uint32_t g_woh[(size_t)ND*ND/2], g_wol[(size_t)ND*ND/2];
__device__ uint32_t g_w1h[(size_t)ND*NDFF/2], g_w1l[(size_t)ND*NDFF/2];
__device__ uint32_t g_w2h[(size_t)ND*NDFF/2], g_w2l[(size_t)ND*NDFF/2];
__device__ float g_q  [BTD];
__device__ float g_k  [(size_t)NB*NL*ND];
__device__ float g_v  [(size_t)NB*NL*ND];
__device__ float g_rel[SCSZ];
__device__ float g_x2 [BTD];

// ------------------------------ helpers ------------------------------------
__device__ __forceinline__ float gelu_exact(float v) {
    return 0.5f * v * (1.0f + erff(v * 0.70710678118654752f));
}

// Pack (x -> low16, y -> high16) bf16x2 hi, plus residual bf16x2 lo.
__device__ __forceinline__ void splitpack(float x, float y, uint32_t& hi, uint32_t& lo) {
    uint32_t h;
    asm("cvt.rn.bf16x2.f32 %0, %1, %2;" : "=r"(h) : "f"(y), "f"(x));
    float hx = __uint_as_float(h << 16);
    float hy = __uint_as_float(h & 0xFFFF0000u);
    uint32_t l;
    asm("cvt.rn.bf16x2.f32 %0, %1, %2;" : "=r"(l) : "f"(y - hy), "f"(x - hx));
    hi = h; lo = l;
}

__device__ __forceinline__ void mma16(float* c, const uint32_t* a, const uint32_t* b) {
    asm volatile("mma.sync.aligned.m16n8k16.row.col.f32.bf16.bf16.f32 "
        "{%0,%1,%2,%3}, {%4,%5,%6,%7}, {%8,%9}, {%0,%1,%2,%3};\n"
        : "+f"(c[0]), "+f"(c[1]), "+f"(c[2]), "+f"(c[3])
        : "r"(a[0]), "r"(a[1]), "r"(a[2]), "r"(a[3]), "r"(b[0]), "r"(b[1]));
}

__device__ __forceinline__ void cp16(uint32_t dst, const void* src) {
    asm volatile("cp.async.cg.shared.global [%0], [%1], 16;\n" :: "r"(dst), "l"(src));
}
#define CP_COMMIT() asm volatile("cp.async.commit_group;\n")
#define CP_WAIT1()  asm volatile("cp.async.wait_group 1;\n")

__device__ __forceinline__ int mskA(int k2) { return ((k2 & 3) << 3) ^ (k2 >> 2); }

// ------------------------- split / pack kernels -----------------------------
// pe packed directly
__global__ void pe_pack(uint32_t* __restrict__ oh, uint32_t* __restrict__ ol) {
    int idx = blockIdx.x * blockDim.x + threadIdx.x;
    if (idx >= NL * ND / 2) return;
    int l = idx >> 9, k2 = idx & 511;
    float pos = (float)(NL - 1 - l);
    float v[2];
#pragma unroll
    for (int t = 0; t < 2; t++) {
        int d = 2 * k2 + t;
        int j = (d < ND / 2) ? d : d - ND / 2;
        float invf = powf(10000.0f, -(2.0f * (float)j) / (float)ND);
        float a = pos * invf;
        v[t] = (d < ND / 2) ? sinf(a) : cosf(a);
    }
    uint32_t h, lo;
    splitpack(v[0], v[1], h, lo);
    oh[idx] = h; ol[idx] = lo;
}

// layer norm -> split planes
__global__ void ln_split(const float* __restrict__ x, const float* __restrict__ g,
                         const float* __restrict__ b,
                         uint32_t* __restrict__ oh, uint32_t* __restrict__ ol) {
    int row = blockIdx.x, tid = threadIdx.x;
    float4 v = *reinterpret_cast<const float4*>(x + (size_t)row * ND + tid * 4);
    __shared__ float red[256];
    red[tid] = v.x + v.y + v.z + v.w; __syncthreads();
    for (int o = 128; o > 0; o >>= 1) { if (tid < o) red[tid] += red[tid + o]; __syncthreads(); }
    float mu = red[0] * (1.0f / ND);
    __syncthreads();
    float dx = v.x - mu, dy = v.y - mu, dz = v.z - mu, dw = v.w - mu;
    red[tid] = dx * dx + dy * dy + dz * dz + dw * dw; __syncthreads();
    for (int o = 128; o > 0; o >>= 1) { if (tid < o) red[tid] += red[tid + o]; __syncthreads(); }
    float rstd = rsqrtf(red[0] * (1.0f / ND) + 1e-5f);
    float4 gg = *reinterpret_cast<const float4*>(g + tid * 4);
    float4 bb = *reinterpret_cast<const float4*>(b + tid * 4);
    float y0 = dx * rstd * gg.x + bb.x;
    float y1 = dy * rstd * gg.y + bb.y;
    float y2 = dz * rstd * gg.z + bb.z;
    float y3 = dw * rstd * gg.w + bb.w;
    uint2 H, L;
    splitpack(y0, y1, H.x, L.x);
    splitpack(y2, y3, H.y, L.y);
    *reinterpret_cast<uint2*>(oh + (size_t)row * 512 + tid * 2) = H;
    *reinterpret_cast<uint2*>(ol + (size_t)row * 512 + tid * 2) = L;
}

// cat planes: mem (split here) ; xn (copy planes)
__global__ void cat_split(const float* __restrict__ mem,
                          const uint32_t* __restrict__ xnh, const uint32_t* __restrict__ xnl,
                          uint32_t* __restrict__ oh, uint32_t* __restrict__ ol) {
    size_t idx = (size_t)blockIdx.x * blockDim.x + threadIdx.x;
    if (idx >= (size_t)NB * NL * 512) return;
    size_t b = idx / ((size_t)NL * 512);
    size_t rem = idx - b * (size_t)NL * 512;
    int l = (int)(rem >> 9), k2 = (int)(rem & 511);
    if (l < NM) {
        float2 m2 = *reinterpret_cast<const float2*>(mem + ((b * NM + l) * ND) + 2 * k2);
        uint32_t h, lo; splitpack(m2.x, m2.y, h, lo);
        oh[idx] = h; ol[idx] = lo;
    } else {
        size_t s = (b * NT + (l - NM)) * 512 + k2;
        oh[idx] = xnh[s]; ol[idx] = xnl[s];
    }
}

// qv = q + bias_v, split
__global__ void qv_split(const float* __restrict__ q, const float* __restrict__ bv,
                         uint32_t* __restrict__ oh, uint32_t* __restrict__ ol) {
    size_t idx = (size_t)blockIdx.x * blockDim.x + threadIdx.x;
    if (idx >= BTD / 2) return;
    int k2 = (int)(idx & 511);
    float2 q2 = *reinterpret_cast<const float2*>(q + 2 * idx);
    float x0 = q2.x + bv[2 * k2], x1 = q2.y + bv[2 * k2 + 1];
    uint32_t h, lo; splitpack(x0, x1, h, lo);
    oh[idx] = h; ol[idx] = lo;
}

// weights: pack across rows (along K): plane [K/2][N]
__global__ void wsplit(const float* __restrict__ W, uint32_t* __restrict__ wh,
                       uint32_t* __restrict__ wl, int K, int N) {
    int idx = blockIdx.x * blockDim.x + threadIdx.x;
    int tot = (K / 2) * (N / 4);
    if (idx >= tot) return;
    int k2 = idx / (N / 4), n4 = (idx % (N / 4)) * 4;
    float4 r0 = *reinterpret_cast<const float4*>(W + (size_t)(2 * k2) * N + n4);
    float4 r1 = *reinterpret_cast<const float4*>(W + (size_t)(2 * k2 + 1) * N + n4);
    uint4 H, L;
    splitpack(r0.x, r1.x, H.x, L.x);
    splitpack(r0.y, r1.y, H.y, L.y);
    splitpack(r0.z, r1.z, H.z, L.z);
    splitpack(r0.w, r1.w, H.w, L.w);
    *reinterpret_cast<uint4*>(wh + (size_t)k2 * N + n4) = H;
    *reinterpret_cast<uint4*>(wl + (size_t)k2 * N + n4) = L;
}

// ------------------- packed-operand GEMM core (cp.async) -------------------
// A planes [M][K/2] (lda2). TRANSB=0: B planes [K/2][N] (ldb). TRANSB=1:
// B planes [N][K/2] (ldb = K/2 stride). C per EPI:
//  0 fp32 | 1 fp32+res | 2 bias->gelu->split | 3 fp32+bias+res | 4 split
template<int TRANSB, int EPI>
__device__ __forceinline__ void mm_core_pk(
    const uint32_t* __restrict__ Ahp, const uint32_t* __restrict__ Alp,
    const uint32_t* __restrict__ Bhp, const uint32_t* __restrict__ Blp,
    float* __restrict__ C, uint32_t* __restrict__ Chp, uint32_t* __restrict__ Clp,
    int K, int lda2, int ldb, int ldc,
    const float* __restrict__ biasC, const float* __restrict__ resC)
{
    constexpr int BM = 128, BN = 128, BK = 16, BK2 = 8, AST = 12;
    constexpr int ASZ = BM * AST;
    constexpr int BSZ = TRANSB ? BM * AST : BK2 * BN;
    extern __shared__ uint32_t sm[];
    uint32_t* Ahs = sm;
    uint32_t* Als = Ahs + 3 * ASZ;
    uint32_t* Bhs = Als + 3 * ASZ;
    uint32_t* Bls = Bhs + 3 * BSZ;

    const int tid = threadIdx.x, lane = tid & 31, w = tid >> 5;
    const int wm = w & 1, wn = w >> 1;
    const int mBase = wm * 64, nBase = wn * 32;
    const int m0 = blockIdx.y * BM, n0 = blockIdx.x * BN;
    const int tig = lane & 3, gid = lane >> 2;

    const int arow = tid >> 1, ac = (tid & 1) * 4;
    const uint32_t* agh = Ahp + (size_t)(m0 + arow) * lda2 + ac;
    const uint32_t* agl = Alp + (size_t)(m0 + arow) * lda2 + ac;
    const uint32_t *bgh, *bgl;
    uint32_t ah_d, al_d, bh_d, bl_d;
    ah_d = (uint32_t)__cvta_generic_to_shared(Ahs + arow * AST + ac);
    al_d = (uint32_t)__cvta_generic_to_shared(Als + arow * AST + ac);
    if (TRANSB) {
        bgh = Bhp + (size_t)(n0 + arow) * ldb + ac;
        bgl = Blp + (size_t)(n0 + arow) * ldb + ac;
        bh_d = (uint32_t)__cvta_generic_to_shared(Bhs + arow * AST + ac);
        bl_d = (uint32_t)__cvta_generic_to_shared(Bls + arow * AST + ac);
    } else {
        int bk2 = tid >> 5, bn4 = (tid & 31) * 4;
        bgh = Bhp + (size_t)bk2 * ldb + n0 + bn4;
        bgl = Blp + (size_t)bk2 * ldb + n0 + bn4;
        int off = bk2 * BN + (bn4 ^ ((bk2 & 3) << 3));
        bh_d = (uint32_t)__cvta_generic_to_shared(Bhs + off);
        bl_d = (uint32_t)__cvta_generic_to_shared(Bls + off);
    }

    auto issue = [&](int s, int t) {
        int k20 = t * BK2;
        cp16(ah_d + s * ASZ * 4, agh + k20);
        cp16(al_d + s * ASZ * 4, agl + k20);
        if (TRANSB) {
            cp16(bh_d + s * BSZ * 4, bgh + k20);
            cp16(bl_d + s * BSZ * 4, bgl + k20);
        } else {
            cp16(bh_d + s * BSZ * 4, bgh + (size_t)k20 * ldb);
            cp16(bl_d + s * BSZ * 4, bgl + (size_t)k20 * ldb);
        }
    };

    float acc[4][4][4];
#pragma unroll
    for (int i = 0; i < 4; i++)
#pragma unroll
        for (int j = 0; j < 4; j++)
#pragma unroll
            for (int r = 0; r < 4; r++) acc[i][j][r] = 0.f;

    const int ntiles = K / BK;
    issue(0, 0); CP_COMMIT();
    issue(1, 1); CP_COMMIT();

    for (int t = 0; t < ntiles; ++t) {
        int s = t - (t / 3) * 3;
        CP_WAIT1();
        __syncthreads();

        const uint32_t* Ab = Ahs + s * ASZ;
        const uint32_t* Alb = Als + s * ASZ;
        const uint32_t* Bb = Bhs + s * BSZ;
        const uint32_t* Blb = Bls + s * BSZ;
        uint32_t ah[4][4], al[4][4], bh[4][2], bl[4][2];
#pragma unroll
        for (int mf = 0; mf < 4; mf++) {
            int m = mBase + mf * 16 + gid;
            ah[mf][0] = Ab [m * AST + tig];       ah[mf][1] = Ab [(m + 8) * AST + tig];
            ah[mf][2] = Ab [m * AST + tig + 4];   ah[mf][3] = Ab [(m + 8) * AST + tig + 4];
            al[mf][0] = Alb[m * AST + tig];       al[mf][1] = Alb[(m + 8) * AST + tig];
            al[mf][2] = Alb[m * AST + tig + 4];   al[mf][3] = Alb[(m + 8) * AST + tig + 4];
        }
#pragma unroll
        for (int nf = 0; nf < 4; nf++) {
            int n = nBase + nf * 8 + gid;
            if (TRANSB) {
                bh[nf][0] = Bb [n * AST + tig];  bh[nf][1] = Bb [n * AST + tig + 4];
                bl[nf][0] = Blb[n * AST + tig];  bl[nf][1] = Blb[n * AST + tig + 4];
            } else {
                int x0 = tig * BN + (n ^ (tig << 3));
                int x1 = (tig + 4) * BN + (n ^ (tig << 3));
                bh[nf][0] = Bb[x0];  bh[nf][1] = Bb[x1];
                bl[nf][0] = Blb[x0]; bl[nf][1] = Blb[x1];
            }
        }
#pragma unroll
        for (int mf = 0; mf < 4; mf++)
#pragma unroll
            for (int nf = 0; nf < 4; nf++) {
                mma16(acc[mf][nf], ah[mf], bh[nf]);
                mma16(acc[mf][nf], ah[mf], bl[nf]);
                mma16(acc[mf][nf], al[mf], bh[nf]);
            }
        __syncthreads();
        if (t + 2 < ntiles) issue((t + 2) - ((t + 2) / 3) * 3, t + 2);
        CP_COMMIT();
    }

    // ------- epilogue -------
#pragma unroll
    for (int mf = 0; mf < 4; mf++) {
        int m = m0 + mBase + mf * 16 + gid;
#pragma unroll
        for (int nf = 0; nf < 4; nf++) {
            int n = n0 + nBase + nf * 8 + tig * 2;
            float v0 = acc[mf][nf][0], v1 = acc[mf][nf][1];
            float v2 = acc[mf][nf][2], v3 = acc[mf][nf][3];
            if (EPI == 2 || EPI == 3) {
                float b0 = biasC[n], b1 = biasC[n + 1];
                v0 += b0; v1 += b1; v2 += b0; v3 += b1;
            }
            if (EPI == 2) {
                v0 = gelu_exact(v0); v1 = gelu_exact(v1);
                v2 = gelu_exact(v2); v3 = gelu_exact(v3);
            }
            if (EPI == 1 || EPI == 3) {
                v0 += resC[(size_t)m * ldc + n];
                v1 += resC[(size_t)m * ldc + n + 1];
                v2 += resC[(size_t)(m + 8) * ldc + n];
                v3 += resC[(size_t)(m + 8) * ldc + n + 1];
            }
            if (EPI == 2 || EPI == 4) {
                uint32_t h0, l0, h1, l1;
                splitpack(v0, v1, h0, l0);
                splitpack(v2, v3, h1, l1);
                Chp[(size_t)m * ldc + (n >> 1)] = h0;  Clp[(size_t)m * ldc + (n >> 1)] = l0;
                Chp[(size_t)(m + 8) * ldc + (n >> 1)] = h1;
                Clp[(size_t)(m + 8) * ldc + (n >> 1)] = l1;
            } else {
                C[(size_t)m * ldc + n] = v0;
                C[(size_t)m * ldc + n + 1] = v1;
                C[(size_t)(m + 8) * ldc + n] = v2;
                C[(size_t)(m + 8) * ldc + n + 1] = v3;
            }
        }
    }
}

#define GSM0 (3 * (128*12*2 + 8*128*2) * 4)    // 61440 B (TRANSB=0)
#define GSM1 (3 * (128*12*2 + 128*12*2) * 4)   // 73728 B (TRANSB=1)

template<int EPI>
__global__ __launch_bounds__(256, 2) void gemm_pk(
    const uint32_t* __restrict__ Ahp, const uint32_t* __restrict__ Alp,
    const uint32_t* __restrict__ Bhp, const uint32_t* __restrict__ Blp,
    float* __restrict__ C, uint32_t* __restrict__ Chp, uint32_t* __restrict__ Clp,
    int K, int lda2, int ldb, int ldc,
    const float* __restrict__ biasC, const float* __restrict__ resC)
{
    mm_core_pk<0, EPI>(Ahp, Alp, Bhp, Blp, C, Chp, Clp, K, lda2, ldb, ldc, biasC, resC);
}

__global__ __launch_bounds__(256, 2) void relraw_pk(
    const uint32_t* __restrict__ qvh, const uint32_t* __restrict__ qvl,
    const uint32_t* __restrict__ rh, const uint32_t* __restrict__ rl,
    float* __restrict__ rel)
{
    int bh = blockIdx.z, b = bh >> 4, hd = bh & 15;
    const uint32_t* Ah = qvh + (size_t)(b * NT) * 512 + hd * 32;
    const uint32_t* Al = qvl + (size_t)(b * NT) * 512 + hd * 32;
    const uint32_t* Bh = rh + hd * 32;
    const uint32_t* Bl = rl + hd * 32;
    float* Cb = rel + (size_t)bh * NT * NL;
    mm_core_pk<1, 0>(Ah, Al, Bh, Bl, Cb, nullptr, nullptr,
                     NDH, 512, 512, NL, nullptr, nullptr);
}

// -------------------- flash-fused attention ---------------------------------
__global__ __launch_bounds__(256) void flash_kernel(
    const float* __restrict__ qg, const float* __restrict__ kg,
    const float* __restrict__ vg, const float* __restrict__ Dg,
    const float* __restrict__ bias_u,
    uint32_t* __restrict__ ctxh, uint32_t* __restrict__ ctxl)
{
    extern __shared__ uint32_t smx[];
    uint32_t* Qh = smx;           uint32_t* Ql = smx + 4096;
    uint32_t* Kh = smx + 8192;    uint32_t* Kl = smx + 12288;
    uint32_t* Vh = smx + 16384;   uint32_t* Vl = smx + 20480;

    const int tid = threadIdx.x, lane = tid & 31, w = tid >> 5;
    const int gid = lane >> 2, tig = lane & 3;
    const int bh = blockIdx.y, b = bh >> 4, hd = bh & 15;
    const int i0 = blockIdx.x * 128;

    const float* qb = qg + (size_t)(b * NT + i0) * ND + hd * NDH;
    const float* kb = kg + (size_t)b * NL * ND + hd * NDH;
    const float* vb = vg + (size_t)b * NL * ND + hd * NDH;
    const float* Db = Dg + (size_t)bh * NT * NL;
    const float* bu = bias_u + hd * NDH;

#pragma unroll
    for (int it = 0; it < 8; it++) {
        int idx = tid + it * 256;
        int row = idx >> 4, c4 = idx & 15;
        float4 t = *reinterpret_cast<const float4*>(qb + (size_t)row * ND + c4 * 4);
        t.x += bu[c4 * 4]; t.y += bu[c4 * 4 + 1]; t.z += bu[c4 * 4 + 2]; t.w += bu[c4 * 4 + 3];
        int k2a = 2 * c4, k2b = 2 * c4 + 1;
        uint32_t h0, l0, h1, l1;
        splitpack(t.x, t.y, h0, l0);
        splitpack(t.z, t.w, h1, l1);
        Qh[k2a * 128 + (row ^ mskA(k2a))] = h0; Ql[k2a * 128 + (row ^ mskA(k2a))] = l0;
        Qh[k2b * 128 + (row ^ mskA(k2b))] = h1; Ql[k2b * 128 + (row ^ mskA(k2b))] = l1;
    }

    const int mBase = w * 16;
    const int iA = i0 + mBase + gid;
    const float* DrowA = Db + (size_t)iA * NL;
    const float* DrowB = DrowA + (size_t)8 * NL;

    float mA = -1e30f, mB = -1e30f, lA = 0.f, lB = 0.f;
    float oacc[8][4];
#pragma unroll
    for (int i = 0; i < 8; i++)
#pragma unroll
        for (int r = 0; r < 4; r++) oacc[i][r] = 0.f;

    for (int jt = 0; jt < NL / 128; jt++) {
        const int j0 = jt * 128;
        __syncthreads();

#pragma unroll
        for (int it = 0; it < 8; it++) {
            int idx = tid + it * 256;
            int row = idx >> 4, c4 = idx & 15;
            float4 t = *reinterpret_cast<const float4*>(kb + (size_t)(j0 + row) * ND + c4 * 4);
            int k2a = 2 * c4, k2b = 2 * c4 + 1;
            uint32_t h0, l0, h1, l1;
            splitpack(t.x, t.y, h0, l0);
            splitpack(t.z, t.w, h1, l1);
            Kh[k2a * 128 + (row ^ mskA(k2a))] = h0; Kl[k2a * 128 + (row ^ mskA(k2a))] = l0;
            Kh[k2b * 128 + (row ^ mskA(k2b))] = h1; Kl[k2b * 128 + (row ^ mskA(k2b))] = l1;
        }
#pragma unroll
        for (int it = 0; it < 4; it++) {
            int idx = tid + it * 256;
            int k2 = idx >> 4, n4 = idx & 15;
            const float* p0 = vb + (size_t)(j0 + 2 * k2) * ND + n4 * 4;
            float4 v0 = *reinterpret_cast<const float4*>(p0);
            float4 v1 = *reinterpret_cast<const float4*>(p0 + ND);
            uint4 H, L;
            splitpack(v0.x, v1.x, H.x, L.x);
            splitpack(v0.y, v1.y, H.y, L.y);
            splitpack(v0.z, v1.z, H.z, L.z);
            splitpack(v0.w, v1.w, H.w, L.w);
            int base = k2 * 64 + ((n4 * 4) ^ ((k2 & 3) << 3));
            *reinterpret_cast<uint4*>(Vh + base) = H;
            *reinterpret_cast<uint4*>(Vl + base) = L;
        }
        __syncthreads();

        float sacc[16][4];
#pragma unroll
        for (int i = 0; i < 16; i++)
#pragma unroll
            for (int r = 0; r < 4; r++) sacc[i][r] = 0.f;

#pragma unroll
        for (int kt = 0; kt < 4; kt++) {
            int k21 = kt * 8 + tig, k22 = k21 + 4;
            int m1 = mskA(k21), m2 = mskA(k22);
            int m = mBase + gid;
            uint32_t ah[4], al[4];
            ah[0] = Qh[k21 * 128 + ( m      ^ m1)];
            ah[1] = Qh[k21 * 128 + ((m + 8) ^ m1)];
            ah[2] = Qh[k22 * 128 + ( m      ^ m2)];
            ah[3] = Qh[k22 * 128 + ((m + 8) ^ m2)];
            al[0] = Ql[k21 * 128 + ( m      ^ m1)];
            al[1] = Ql[k21 * 128 + ((m + 8) ^ m1)];
            al[2] = Ql[k22 * 128 + ( m      ^ m2)];
            al[3] = Ql[k22 * 128 + ((m + 8) ^ m2)];
#pragma unroll
            for (int nf = 0; nf < 16; nf++) {
                int n = nf * 8 + gid;
                uint32_t bhv[2] = { Kh[k21 * 128 + (n ^ m1)], Kh[k22 * 128 + (n ^ m2)] };
                uint32_t blv[2] = { Kl[k21 * 128 + (n ^ m1)], Kl[k22 * 128 + (n ^ m2)] };
                mma16(sacc[nf], ah, bhv);
                mma16(sacc[nf], ah, blv);
                mma16(sacc[nf], al, bhv);
            }
        }

        const int jc = j0 + 2 * tig;
        float mAt = -1e30f, mBt = -1e30f;
#pragma unroll
        for (int nf = 0; nf < 16; nf++) {
            int j = jc + nf * 8;
            int d0 = j - iA, d1 = d0 + 1;
            int e0 = d0 - 8, e1 = e0 + 1;
            float D0 = DrowA[d0 + (d0 <= 1024 ? 1023 : 1022)];
            float D1 = DrowA[d1 + (d1 <= 1024 ? 1023 : 1022)];
            float E0 = DrowB[e0 + (e0 <= 1024 ? 1023 : 1022)];
            float E1 = DrowB[e1 + (e1 <= 1024 ? 1023 : 1022)];
            if (d0 == 1025) D0 = 0.f;
            if (d1 == 1025) D1 = 0.f;
            if (e0 == 1025) E0 = 0.f;
            if (e1 == 1025) E1 = 0.f;
            float s0 = (sacc[nf][0] + D0) * 0.125f;
            float s1 = (sacc[nf][1] + D1) * 0.125f;
            float s2 = (sacc[nf][2] + E0) * 0.125f;
            float s3 = (sacc[nf][3] + E1) * 0.125f;
            sacc[nf][0] = s0; sacc[nf][1] = s1; sacc[nf][2] = s2; sacc[nf][3] = s3;
            mAt = fmaxf(mAt, fmaxf(s0, s1));
            mBt = fmaxf(mBt, fmaxf(s2, s3));
        }
        mAt = fmaxf(mAt, __shfl_xor_sync(0xFFFFFFFFu, mAt, 1));
        mAt = fmaxf(mAt, __shfl_xor_sync(0xFFFFFFFFu, mAt, 2));
        mBt = fmaxf(mBt, __shfl_xor_sync(0xFFFFFFFFu, mBt, 1));
        mBt = fmaxf(mBt, __shfl_xor_sync(0xFFFFFFFFu, mBt, 2));

        float mAn = fmaxf(mA, mAt), mBn = fmaxf(mB, mBt);
        float cA = __expf(mA - mAn), cB = __expf(mB - mBn);
        mA = mAn; mB = mBn;
        lA *= cA; lB *= cB;
#pragma unroll
        for (int nfv = 0; nfv < 8; nfv++) {
            oacc[nfv][0] *= cA; oacc[nfv][1] *= cA;
            oacc[nfv][2] *= cB; oacc[nfv][3] *= cB;
        }

        uint32_t pah[8][4], pal[8][4];
#pragma unroll
        for (int kt = 0; kt < 8; kt++) {
            float p00 = __expf(sacc[2*kt  ][0] - mA), p01 = __expf(sacc[2*kt  ][1] - mA);
            float p02 = __expf(sacc[2*kt  ][2] - mB), p03 = __expf(sacc[2*kt  ][3] - mB);
            float p10 = __expf(sacc[2*kt+1][0] - mA), p11 = __expf(sacc[2*kt+1][1] - mA);
            float p12 = __expf(sacc[2*kt+1][2] - mB), p13 = __expf(sacc[2*kt+1][3] - mB);
            lA += p00 + p01 + p10 + p11;
            lB += p02 + p03 + p12 + p13;
            splitpack(p00, p01, pah[kt][0], pal[kt][0]);
            splitpack(p02, p03, pah[kt][1], pal[kt][1]);
            splitpack(p10, p11, pah[kt][2], pal[kt][2]);
            splitpack(p12, p13, pah[kt][3], pal[kt][3]);
        }

#pragma unroll
        for (int kt = 0; kt < 8; kt++) {
            int k21 = kt * 8 + tig, k22 = k21 + 4;
            int mv = tig << 3;
#pragma unroll
            for (int nfv = 0; nfv < 8; nfv++) {
                int n = nfv * 8 + gid;
                uint32_t vbh[2] = { Vh[k21 * 64 + (n ^ mv)], Vh[k22 * 64 + (n ^ mv)] };
                uint32_t vbl[2] = { Vl[k21 * 64 + (n ^ mv)], Vl[k22 * 64 + (n ^ mv)] };
                mma16(oacc[nfv], pah[kt], vbh);
                mma16(oacc[nfv], pah[kt], vbl);
                mma16(oacc[nfv], pal[kt], vbh);
            }
        }
    }

    lA += __shfl_xor_sync(0xFFFFFFFFu, lA, 1);
    lA += __shfl_xor_sync(0xFFFFFFFFu, lA, 2);
    lB += __shfl_xor_sync(0xFFFFFFFFu, lB, 1);
    lB += __shfl_xor_sync(0xFFFFFFFFu, lB, 2);
    float invA = 1.0f / lA, invB = 1.0f / lB;
    const size_t gA = (size_t)(b * NT + i0 + mBase + gid);
    const size_t gB = gA + 8;
#pragma unroll
    for (int nfv = 0; nfv < 8; nfv++) {
        int colh = hd * 32 + nfv * 4 + tig;
        uint32_t h0, l0, h1, l1;
        splitpack(oacc[nfv][0] * invA, oacc[nfv][1] * invA, h0, l0);
        splitpack(oacc[nfv][2] * invB, oacc[nfv][3] * invB, h1, l1);
        ctxh[gA * 512 + colh] = h0; ctxl[gA * 512 + colh] = l0;
        ctxh[gB * 512 + colh] = h1; ctxl[gB * 512 + colh] = l1;
    }
}

#define FLASH_SMEM (24576 * 4)

// ------------------------------ launch -------------------------------------
extern "C" void kernel_launch(void* const* d_in, const int* in_sizes, int n_in,
                              void* d_out, int out_size) {
    const float* x      = (const float*)d_in[0];
    const float* mem    = (const float*)d_in[1];
    const float* Wq     = (const float*)d_in[2];
    const float* Wk     = (const float*)d_in[3];
    const float* Wv     = (const float*)d_in[4];
    const float* Wr     = (const float*)d_in[5];
    const float* Wo     = (const float*)d_in[6];
    const float* bias_u = (const float*)d_in[7];
    const float* bias_v = (const float*)d_in[8];
    const float* ln1_g  = (const float*)d_in[9];
    const float* ln1_b  = (const float*)d_in[10];
    const float* ln2_g  = (const float*)d_in[11];
    const float* ln2_b  = (const float*)d_in[12];
    const float* W1     = (const float*)d_in[13];
    const float* b1     = (const float*)d_in[14];
    const float* W2     = (const float*)d_in[15];
    const float* b2     = (const float*)d_in[16];
    float* out = (float*)d_out;

    uint32_t *xnh,*xnl,*cath,*catl,*peh,*pel,*qvh,*qvl,*rh,*rl,*ctxh,*ctxl,*xfh,*xfl,*ffhh,*ffhl;
    uint32_t *wqh,*wql,*wkh,*wkl,*wvh,*wvl,*wrh,*wrl,*woh,*wol,*w1h,*w1l,*w2h,*w2l;
    float *q,*k,*v,*rel,*x2;
    cudaGetSymbolAddress((void**)&xnh, g_xnh);   cudaGetSymbolAddress((void**)&xnl, g_xnl);
    cudaGetSymbolAddress((void**)&cath, g_cath); cudaGetSymbolAddress((void**)&catl, g_catl);
    cudaGetSymbolAddress((void**)&peh, g_peh);   cudaGetSymbolAddress((void**)&pel, g_pel);
    cudaGetSymbolAddress((void**)&qvh, g_qvh);   cudaGetSymbolAddress((void**)&qvl, g_qvl);
    cudaGetSymbolAddress((void**)&rh, g_rh);     cudaGetSymbolAddress((void**)&rl, g_rl);
    cudaGetSymbolAddress((void**)&ctxh, g_ctxh); cudaGetSymbolAddress((void**)&ctxl, g_ctxl);
    cudaGetSymbolAddress((void**)&xfh, g_xfh);   cudaGetSymbolAddress((void**)&xfl, g_xfl);
    cudaGetSymbolAddress((void**)&ffhh, g_ffhh); cudaGetSymbolAddress((void**)&ffhl, g_ffhl);
    cudaGetSymbolAddress((void**)&wqh, g_wqh);   cudaGetSymbolAddress((void**)&wql, g_wql);
    cudaGetSymbolAddress((void**)&wkh, g_wkh);   cudaGetSymbolAddress((void**)&wkl, g_wkl);
    cudaGetSymbolAddress((void**)&wvh, g_wvh);   cudaGetSymbolAddress((void**)&wvl, g_wvl);
    cudaGetSymbolAddress((void**)&wrh, g_wrh);   cudaGetSymbolAddress((void**)&wrl, g_wrl);
    cudaGetSymbolAddress((void**)&woh, g_woh);   cudaGetSymbolAddress((void**)&wol, g_wol);
    cudaGetSymbolAddress((void**)&w1h, g_w1h);   cudaGetSymbolAddress((void**)&w1l, g_w1l);
    cudaGetSymbolAddress((void**)&w2h, g_w2h);   cudaGetSymbolAddress((void**)&w2l, g_w2l);
    cudaGetSymbolAddress((void**)&q, g_q);
    cudaGetSymbolAddress((void**)&k, g_k);
    cudaGetSymbolAddress((void**)&v, g_v);
    cudaGetSymbolAddress((void**)&rel, g_rel);
    cudaGetSymbolAddress((void**)&x2, g_x2);

    cudaFuncSetAttribute(gemm_pk<0>, cudaFuncAttributeMaxDynamicSharedMemorySize, GSM0);
    cudaFuncSetAttribute(gemm_pk<1>, cudaFuncAttributeMaxDynamicSharedMemorySize, GSM0);
    cudaFuncSetAttribute(gemm_pk<2>, cudaFuncAttributeMaxDynamicSharedMemorySize, GSM0);
    cudaFuncSetAttribute(gemm_pk<3>, cudaFuncAttributeMaxDynamicSharedMemorySize, GSM0);
    cudaFuncSetAttribute(gemm_pk<4>, cudaFuncAttributeMaxDynamicSharedMemorySize, GSM0);
    cudaFuncSetAttribute(relraw_pk,  cudaFuncAttributeMaxDynamicSharedMemorySize, GSM1);
    cudaFuncSetAttribute(flash_kernel, cudaFuncAttributeMaxDynamicSharedMemorySize, FLASH_SMEM);

    // packing / splits
    pe_pack<<<(NL * ND / 2 + 255) / 256, 256>>>(peh, pel);
    ln_split<<<NB * NT, 256>>>(x, ln1_g, ln1_b, xnh, xnl);
    cat_split<<<(unsigned)(((size_t)NB * NL * 512 + 255) / 256), 256>>>(mem, xnh, xnl, cath, catl);
    wsplit<<<(512 * 1024 + 255) / 256, 256>>>(Wq, wqh, wql, ND, ND);
    wsplit<<<(512 * 1024 + 255) / 256, 256>>>(Wk, wkh, wkl, ND, ND);
    wsplit<<<(512 * 1024 + 255) / 256, 256>>>(Wv, wvh, wvl, ND, ND);
    wsplit<<<(512 * 1024 + 255) / 256, 256>>>(Wr, wrh, wrl, ND, ND);
    wsplit<<<(512 * 1024 + 255) / 256, 256>>>(Wo, woh, wol, ND, ND);
    wsplit<<<(512 * 4096 + 255) / 256, 256>>>(W1, w1h, w1l, ND, NDFF);
    wsplit<<<(2048 * 1024 + 255) / 256, 256>>>(W2, w2h, w2l, NDFF, ND);

    // projections
    gemm_pk<0><<<dim3(8, 32), 256, GSM0>>>(xnh, xnl, wqh, wql, q, nullptr, nullptr,
                                           ND, 512, ND, ND, nullptr, nullptr);
    gemm_pk<0><<<dim3(8, 64), 256, GSM0>>>(cath, catl, wkh, wkl, k, nullptr, nullptr,
                                           ND, 512, ND, ND, nullptr, nullptr);
    gemm_pk<0><<<dim3(8, 64), 256, GSM0>>>(cath, catl, wvh, wvl, v, nullptr, nullptr,
                                           ND, 512, ND, ND, nullptr, nullptr);
    gemm_pk<4><<<dim3(8, 16), 256, GSM0>>>(peh, pel, wrh, wrl, nullptr, rh, rl,
                                           ND, 512, ND, 512, nullptr, nullptr);

    // qv = q + bias_v (split), then raw rel logits
    qv_split<<<(unsigned)((BTD / 2 + 255) / 256), 256>>>(q, bias_v, qvh, qvl);
    relraw_pk<<<dim3(16, 8, NB * NH), 256, GSM1>>>(qvh, qvl, rh, rl, rel);

    // flash attention -> ctx planes
    flash_kernel<<<dim3(NT / 128, NB * NH), 256, FLASH_SMEM>>>(q, k, v, rel, bias_u, ctxh, ctxl);

    // x2 = ctx @ Wo + x
    gemm_pk<1><<<dim3(8, 32), 256, GSM0>>>(ctxh, ctxl, woh, wol, x2, nullptr, nullptr,
                                           ND, 512, ND, ND, nullptr, x);
    // xf planes = LN2(x2)
    ln_split<<<NB * NT, 256>>>(x2, ln2_g, ln2_b, xfh, xfl);
    // ffh planes = gelu(xf @ W1 + b1)
    gemm_pk<2><<<dim3(32, 32), 256, GSM0>>>(xfh, xfl, w1h, w1l, nullptr, ffhh, ffhl,
                                            ND, 512, NDFF, 2048, b1, nullptr);
    // out = ffh @ W2 + b2 + x2
    gemm_pk<3><<<dim3(8, 32), 256, GSM0>>>(ffhh, ffhl, w2h, w2l, out, nullptr, nullptr,
                                           NDFF, 2048, ND, ND, b2, x2);

    // new_mem = x
    if ((size_t)out_size >= 2 * BTD) {
        cudaMemcpyAsync(out + BTD, x, BTD * sizeof(float), cudaMemcpyDeviceToDevice);
    }
}